// round 11
// baseline (speedup 1.0000x reference)
#include <cuda_runtime.h>
#include <math.h>

#define NN 80000
#define NE 1280000
#define NET (NE + NN)
#define NGR 256
#define NB5 157          // ceil(NN/512)
#define KP 136
#define WPAD 56

// ---------------- static device scratch (zero at entry, restored at exit) ----------------
__device__ int g_deg[NN];          // ZERO at entry (restored by k_final)
__device__ int g_rowptr[NN + 1];
__device__ int g_cursor[NN];
__device__ int g_col[NET];
__device__ int g_bsum[NB5];
__device__ int g_boff[NB5];
__device__ int g_tick;             // ZERO at entry
__device__ int g_flag;             // ZERO at entry
__device__ float g_h[(size_t)NN * 54];
__device__ float g_o[(size_t)NN * 4];
__device__ float g_W2p[KP * WPAD];
__device__ float g_als3[NN];
__device__ float g_ald3[NN];
__device__ float4 g_als[NN];
__device__ float4 g_ald[NN];
__device__ unsigned g_pool[NGR * 4];  // ZERO at entry (0 < enc(-inf), acts as -infinity)
__device__ int g_nz;

__device__ __forceinline__ unsigned enc(float f) {
    unsigned u = __float_as_uint(f);
    return (u & 0x80000000u) ? ~u : (u | 0x80000000u);
}
__device__ __forceinline__ float dec(unsigned u) {
    return __uint_as_float((u & 0x80000000u) ? (u ^ 0x80000000u) : ~u);
}
__device__ __forceinline__ long long ld_idx(const void* p, long long i, bool is64) {
    if (is64) return ((const long long*)p)[i];
    return (long long)((const int*)p)[i];
}

// ---------------- 1: layer-1 logits from x + W2 pad + dtype sniff + rowptr[NN] ----------------
__global__ void k_alpha_x(const float* __restrict__ x, const float* __restrict__ W1,
                          const float* __restrict__ a_src, const float* __restrict__ a_dst,
                          const float* __restrict__ W2, const int* ei32) {
    __shared__ float v[2][3][9];
    int t = threadIdx.x;
    int gi = blockIdx.x * blockDim.x + t;
    // W2 pad (first 30 blocks' threads)
    if (gi < KP * WPAD) {
        int k = gi / WPAD, c = gi - k * WPAD;
        g_W2p[gi] = (k < 135 && c < 54) ? W2[k * 54 + c] : 0.f;
    }
    if (gi == 0) g_rowptr[NN] = NET;
    // dtype sniff (block 0, warp 0)
    if (blockIdx.x == 0 && t < 32) {
        int nz = 0;
        for (int j = t; j < 512; j += 32)
            if (ei32[2 * j + 1] != 0) nz++;
        #pragma unroll
        for (int o = 16; o; o >>= 1) nz += __shfl_xor_sync(0xffffffffu, nz, o);
        if (t == 0) g_nz = nz;   // 0 => int64
    }
    // v-vector precompute (per block)
    if (t < 54) {
        int side = t / 27, r = t % 27;
        int h = r / 9, k = r % 9;
        const float* a = side ? a_dst : a_src;
        float s = 0.f;
        for (int c = 0; c < 45; c++)
            s += __ldg(&W1[k * 135 + h * 45 + c]) * __ldg(&a[h * 45 + c]);
        v[side][h][k] = s;
    }
    __syncthreads();
    int n = gi;
    if (n >= NN) return;
    float xv[9];
    #pragma unroll
    for (int k = 0; k < 9; k++) xv[k] = x[(size_t)n * 9 + k];
    float s[3], d[3];
    #pragma unroll
    for (int h = 0; h < 3; h++) {
        float ss = 0.f, dd = 0.f;
        #pragma unroll
        for (int k = 0; k < 9; k++) {
            ss += xv[k] * v[0][h][k];
            dd += xv[k] * v[1][h][k];
        }
        s[h] = ss; d[h] = dd;
    }
    g_als[n] = make_float4(s[0], s[1], s[2], 0.f);
    g_ald[n] = make_float4(d[0], d[1], d[2], 0.f);
}

// ---------------- 2: degree count ----------------
__global__ void k_count(const void* ei) {
    int e = blockIdx.x * blockDim.x + threadIdx.x;
    if (e >= NE) return;
    bool is64 = (g_nz == 0);
    int dst = (int)ld_idx(ei, (long long)NE + e, is64);
    atomicAdd(&g_deg[dst], 1);
}

// ---------------- 3: single-pass exclusive scan of (deg+1) -> rowptr/cursor ----------------
__global__ void k_scanall() {
    __shared__ int sm[512];
    __shared__ int s_last;
    __shared__ int s_off;
    int b = blockIdx.x, t = threadIdx.x;
    int i = b * 512 + t;
    int v = (i < NN) ? g_deg[i] + 1 : 0;   // +1 = self loop
    sm[t] = v;
    __syncthreads();
    #pragma unroll
    for (int off = 1; off < 512; off <<= 1) {
        int u = (t >= off) ? sm[t - off] : 0;
        __syncthreads();
        sm[t] += u;
        __syncthreads();
    }
    int incl = sm[t];
    int total = sm[511];
    __syncthreads();
    if (t == 0) {
        g_bsum[b] = total;
        __threadfence();
        int tk = atomicAdd(&g_tick, 1);
        s_last = (tk == NB5 - 1);
    }
    __syncthreads();
    if (s_last) {
        int u = (t < NB5) ? g_bsum[t] : 0;
        sm[t] = u;
        __syncthreads();
        #pragma unroll
        for (int off = 1; off < 512; off <<= 1) {
            int w = (t >= off) ? sm[t - off] : 0;
            __syncthreads();
            sm[t] += w;
            __syncthreads();
        }
        if (t < NB5) g_boff[t] = sm[t] - u;   // exclusive
        __threadfence();
        if (t == 0) atomicExch(&g_flag, 1);
    } else {
        if (t == 0) {
            while (atomicAdd(&g_flag, 0) == 0) __nanosleep(64);
        }
    }
    __syncthreads();
    if (t == 0) s_off = atomicAdd(&g_boff[b], 0);
    __syncthreads();
    if (i < NN) {
        int p = s_off + incl - v;
        g_rowptr[i] = p;
        g_cursor[i] = p;
    }
}

// ---------------- 4: CSR fill ----------------
__global__ void k_fill(const void* ei) {
    int e = blockIdx.x * blockDim.x + threadIdx.x;
    if (e >= NET) return;
    bool is64 = (g_nz == 0);
    int s, d;
    if (e < NE) {
        s = (int)ld_idx(ei, e, is64);
        d = (int)ld_idx(ei, (long long)NE + e, is64);
    } else {
        s = d = e - NE;
    }
    int pos = atomicAdd(&g_cursor[d], 1);
    g_col[pos] = s;
}

// ---------------- 5: fused aggx + map1 + gemm2 + alpha2 ----------------
// phase 1: warp-per-node CSR gather of x (27 accumulators) -> smem xa
// phase 2: o1 tile (64x135) in smem -> 135->54 GEMM -> Y + layer-2 logits
__global__ void k_gemmA(const float* __restrict__ x,
                        const float* __restrict__ W1, const float* __restrict__ b1,
                        float* __restrict__ Y,
                        const float* __restrict__ a_src, const float* __restrict__ a_dst) {
    constexpr int NPB = 64;
    __shared__ __align__(16) float xs[NPB * KP];
    __shared__ float xa[NPB * 28];
    int tid = threadIdx.x;
    int lane = tid & 31;
    int w = tid >> 5;
    int nodeBase = blockIdx.x * NPB;

    // ---- phase 1: each warp aggregates 8 nodes ----
    int hh = lane / 9, cc = lane - hh * 9;
    bool act = lane < 27;
    for (int q = 0; q < 8; q++) {
        int r = w * 8 + q;
        int n = nodeBase + r;
        int beg = g_rowptr[n], end = g_rowptr[n + 1];
        float4 ald4 = g_ald[n];
        float aldv[3] = { ald4.x, ald4.y, ald4.z };
        float acc = 0.f;
        float ssum[3] = { 0.f, 0.f, 0.f };

        for (int base = beg; base < end; base += 32) {
            int cnt = min(32, end - base);
            int s_l = 0;
            float e_l[3] = { 0.f, 0.f, 0.f };
            if (lane < cnt) {
                s_l = g_col[base + lane];
                float4 a = g_als[s_l];
                float av[3] = { a.x, a.y, a.z };
                #pragma unroll
                for (int h = 0; h < 3; h++) {
                    float al = av[h] + aldv[h];
                    al = (al > 0.f) ? al : 0.2f * al;
                    e_l[h] = __expf(fminf(al, 80.f));
                }
            }
            #pragma unroll
            for (int h = 0; h < 3; h++) ssum[h] += e_l[h];

            int jj = 0;
            for (; jj + 4 <= cnt; jj += 4) {
                int s0 = __shfl_sync(0xffffffffu, s_l, jj + 0);
                int s1 = __shfl_sync(0xffffffffu, s_l, jj + 1);
                int s2 = __shfl_sync(0xffffffffu, s_l, jj + 2);
                int s3 = __shfl_sync(0xffffffffu, s_l, jj + 3);
                float w0a = __shfl_sync(0xffffffffu, e_l[0], jj + 0);
                float w0b = __shfl_sync(0xffffffffu, e_l[1], jj + 0);
                float w0c = __shfl_sync(0xffffffffu, e_l[2], jj + 0);
                float w1a = __shfl_sync(0xffffffffu, e_l[0], jj + 1);
                float w1b = __shfl_sync(0xffffffffu, e_l[1], jj + 1);
                float w1c = __shfl_sync(0xffffffffu, e_l[2], jj + 1);
                float w2a = __shfl_sync(0xffffffffu, e_l[0], jj + 2);
                float w2b = __shfl_sync(0xffffffffu, e_l[1], jj + 2);
                float w2c = __shfl_sync(0xffffffffu, e_l[2], jj + 2);
                float w3a = __shfl_sync(0xffffffffu, e_l[0], jj + 3);
                float w3b = __shfl_sync(0xffffffffu, e_l[1], jj + 3);
                float w3c = __shfl_sync(0xffffffffu, e_l[2], jj + 3);
                if (act) {
                    float x0 = __ldg(&x[(size_t)s0 * 9 + cc]);
                    float x1 = __ldg(&x[(size_t)s1 * 9 + cc]);
                    float x2 = __ldg(&x[(size_t)s2 * 9 + cc]);
                    float x3 = __ldg(&x[(size_t)s3 * 9 + cc]);
                    float wa = (hh == 0) ? w0a : (hh == 1) ? w0b : w0c;
                    float wb = (hh == 0) ? w1a : (hh == 1) ? w1b : w1c;
                    float wc = (hh == 0) ? w2a : (hh == 1) ? w2b : w2c;
                    float wd = (hh == 0) ? w3a : (hh == 1) ? w3b : w3c;
                    acc += wa * x0;
                    acc += wb * x1;
                    acc += wc * x2;
                    acc += wd * x3;
                }
            }
            for (; jj < cnt; jj++) {
                int s = __shfl_sync(0xffffffffu, s_l, jj);
                float wa0 = __shfl_sync(0xffffffffu, e_l[0], jj);
                float wa1 = __shfl_sync(0xffffffffu, e_l[1], jj);
                float wa2 = __shfl_sync(0xffffffffu, e_l[2], jj);
                if (act) {
                    float xv = __ldg(&x[(size_t)s * 9 + cc]);
                    float ww = (hh == 0) ? wa0 : (hh == 1) ? wa1 : wa2;
                    acc += ww * xv;
                }
            }
        }
        #pragma unroll
        for (int h = 0; h < 3; h++)
            #pragma unroll
            for (int o = 16; o; o >>= 1)
                ssum[h] += __shfl_xor_sync(0xffffffffu, ssum[h], o);
        if (act)
            xa[r * 28 + lane] = acc / (ssum[hh] + 1e-16f);
    }
    __syncthreads();

    // ---- phase 2a: o1 tile = relu(xa @ W1 + b1) into xs ----
    for (int i = tid; i < NPB * KP; i += 256) {
        int r = i / KP, c = i - r * KP;
        float o = 0.f;
        if (c < 135) {
            int h = c / 45;
            const float* ap = xa + r * 28 + h * 9;
            float s = 0.f;
            #pragma unroll
            for (int k = 0; k < 9; k++)
                s += ap[k] * __ldg(&W1[k * 135 + c]);
            o = fmaxf(s + __ldg(&b1[c]), 0.f);
        }
        xs[i] = o;
    }
    __syncthreads();

    // ---- phase 2b: GEMM 135->54 + fused layer-2 logits ----
    int ng = tid / 16, j = tid & 15;
    int c0 = j * 4;
    float acc2[4][4];
    #pragma unroll
    for (int q = 0; q < 4; q++)
        #pragma unroll
        for (int m = 0; m < 4; m++) acc2[q][m] = 0.f;
    const float* xp = xs + (ng * 4) * KP;
    for (int k4 = 0; k4 < KP / 4; k4++) {
        float xr0[4], xr1[4], xr2[4], xr3[4];
        *(float4*)xr0 = *(const float4*)&xp[k4 * 4];
        *(float4*)xr1 = *(const float4*)&xp[KP + k4 * 4];
        *(float4*)xr2 = *(const float4*)&xp[2 * KP + k4 * 4];
        *(float4*)xr3 = *(const float4*)&xp[3 * KP + k4 * 4];
        #pragma unroll
        for (int kk = 0; kk < 4; kk++) {
            float wr[4];
            *(float4*)wr = __ldg((const float4*)&g_W2p[(k4 * 4 + kk) * WPAD + c0]);
            #pragma unroll
            for (int m = 0; m < 4; m++) {
                acc2[0][m] += xr0[kk] * wr[m];
                acc2[1][m] += xr1[kk] * wr[m];
                acc2[2][m] += xr2[kk] * wr[m];
                acc2[3][m] += xr3[kk] * wr[m];
            }
        }
    }
    float as_c[4], ad_c[4];
    #pragma unroll
    for (int m = 0; m < 4; m++) {
        int c = c0 + m;
        as_c[m] = (c < 54) ? __ldg(&a_src[c]) : 0.f;
        ad_c[m] = (c < 54) ? __ldg(&a_dst[c]) : 0.f;
    }
    #pragma unroll
    for (int q = 0; q < 4; q++) {
        int n = nodeBase + ng * 4 + q;
        float ps0 = 0.f, ps1 = 0.f, ps2 = 0.f;
        float pd0 = 0.f, pd1 = 0.f, pd2 = 0.f;
        #pragma unroll
        for (int m = 0; m < 4; m++) {
            int c = c0 + m;
            if (c < 54) {
                Y[(size_t)n * 54 + c] = acc2[q][m];
                int h = c / 18;
                float vs = acc2[q][m] * as_c[m];
                float vd = acc2[q][m] * ad_c[m];
                if (h == 0) { ps0 += vs; pd0 += vd; }
                else if (h == 1) { ps1 += vs; pd1 += vd; }
                else { ps2 += vs; pd2 += vd; }
            }
        }
        #pragma unroll
        for (int o = 8; o; o >>= 1) {
            ps0 += __shfl_xor_sync(0xffffffffu, ps0, o);
            ps1 += __shfl_xor_sync(0xffffffffu, ps1, o);
            ps2 += __shfl_xor_sync(0xffffffffu, ps2, o);
            pd0 += __shfl_xor_sync(0xffffffffu, pd0, o);
            pd1 += __shfl_xor_sync(0xffffffffu, pd1, o);
            pd2 += __shfl_xor_sync(0xffffffffu, pd2, o);
        }
        if (j == 0) {
            g_als[n] = make_float4(ps0, ps1, ps2, 0.f);
            g_ald[n] = make_float4(pd0, pd1, pd2, 0.f);
        }
    }
}

// ---------------- 6: agg2 + fused gemm3 + layer-3 logits ----------------
__global__ void k_agg2(const float* __restrict__ hfeat,
                       const float* __restrict__ bias,
                       const float* __restrict__ W3,
                       const float* __restrict__ as3, const float* __restrict__ ad3,
                       float* __restrict__ h3out) {
    int wid = (blockIdx.x * blockDim.x + threadIdx.x) >> 5;
    if (wid >= NN) return;
    int lane = threadIdx.x & 31;
    int n = wid;
    bool act = lane < 27;
    int c0 = 2 * lane;
    int hd = lane / 9;
    int beg = g_rowptr[n], end = g_rowptr[n + 1];
    float4 ald4 = g_ald[n];
    float aldv[3] = { ald4.x, ald4.y, ald4.z };
    float2 acc = make_float2(0.f, 0.f);
    float ssum0 = 0.f, ssum1 = 0.f, ssum2 = 0.f;

    for (int base = beg; base < end; base += 32) {
        int cnt = min(32, end - base);
        int s_l = 0;
        float e_l[3] = { 0.f, 0.f, 0.f };
        if (lane < cnt) {
            s_l = g_col[base + lane];
            float4 a = g_als[s_l];
            float av[3] = { a.x, a.y, a.z };
            #pragma unroll
            for (int h = 0; h < 3; h++) {
                float al = av[h] + aldv[h];
                al = (al > 0.f) ? al : 0.2f * al;
                e_l[h] = __expf(fminf(al, 80.f));
            }
        }
        ssum0 += e_l[0]; ssum1 += e_l[1]; ssum2 += e_l[2];

        int jj = 0;
        for (; jj + 4 <= cnt; jj += 4) {
            int s0 = __shfl_sync(0xffffffffu, s_l, jj + 0);
            int s1 = __shfl_sync(0xffffffffu, s_l, jj + 1);
            int s2 = __shfl_sync(0xffffffffu, s_l, jj + 2);
            int s3 = __shfl_sync(0xffffffffu, s_l, jj + 3);
            float w0a = __shfl_sync(0xffffffffu, e_l[0], jj + 0);
            float w0b = __shfl_sync(0xffffffffu, e_l[1], jj + 0);
            float w0c = __shfl_sync(0xffffffffu, e_l[2], jj + 0);
            float w1a = __shfl_sync(0xffffffffu, e_l[0], jj + 1);
            float w1b = __shfl_sync(0xffffffffu, e_l[1], jj + 1);
            float w1c = __shfl_sync(0xffffffffu, e_l[2], jj + 1);
            float w2a = __shfl_sync(0xffffffffu, e_l[0], jj + 2);
            float w2b = __shfl_sync(0xffffffffu, e_l[1], jj + 2);
            float w2c = __shfl_sync(0xffffffffu, e_l[2], jj + 2);
            float w3a = __shfl_sync(0xffffffffu, e_l[0], jj + 3);
            float w3b = __shfl_sync(0xffffffffu, e_l[1], jj + 3);
            float w3c = __shfl_sync(0xffffffffu, e_l[2], jj + 3);
            if (act) {
                float2 g0 = *(const float2*)&hfeat[(size_t)s0 * 54 + c0];
                float2 g1 = *(const float2*)&hfeat[(size_t)s1 * 54 + c0];
                float2 g2 = *(const float2*)&hfeat[(size_t)s2 * 54 + c0];
                float2 g3 = *(const float2*)&hfeat[(size_t)s3 * 54 + c0];
                float wa = (hd == 0) ? w0a : (hd == 1) ? w0b : w0c;
                float wb = (hd == 0) ? w1a : (hd == 1) ? w1b : w1c;
                float wc = (hd == 0) ? w2a : (hd == 1) ? w2b : w2c;
                float wd = (hd == 0) ? w3a : (hd == 1) ? w3b : w3c;
                acc.x += wa * g0.x; acc.y += wa * g0.y;
                acc.x += wb * g1.x; acc.y += wb * g1.y;
                acc.x += wc * g2.x; acc.y += wc * g2.y;
                acc.x += wd * g3.x; acc.y += wd * g3.y;
            }
        }
        for (; jj < cnt; jj++) {
            int s = __shfl_sync(0xffffffffu, s_l, jj);
            float wa0 = __shfl_sync(0xffffffffu, e_l[0], jj);
            float wa1 = __shfl_sync(0xffffffffu, e_l[1], jj);
            float wa2 = __shfl_sync(0xffffffffu, e_l[2], jj);
            if (act) {
                float2 g = *(const float2*)&hfeat[(size_t)s * 54 + c0];
                float ww = (hd == 0) ? wa0 : (hd == 1) ? wa1 : wa2;
                acc.x += ww * g.x; acc.y += ww * g.y;
            }
        }
    }
    #pragma unroll
    for (int o = 16; o; o >>= 1) {
        ssum0 += __shfl_xor_sync(0xffffffffu, ssum0, o);
        ssum1 += __shfl_xor_sync(0xffffffffu, ssum1, o);
        ssum2 += __shfl_xor_sync(0xffffffffu, ssum2, o);
    }
    float2 o2 = make_float2(0.f, 0.f);
    if (act) {
        float ss = (hd == 0) ? ssum0 : (hd == 1) ? ssum1 : ssum2;
        float inv = 1.f / (ss + 1e-16f);
        o2.x = fmaxf(acc.x * inv + __ldg(&bias[c0]), 0.f);
        o2.y = fmaxf(acc.y * inv + __ldg(&bias[c0 + 1]), 0.f);
    }
    float t0 = 0.f, t1 = 0.f, t2 = 0.f, t3 = 0.f;
    if (act) {
        float4 wr0 = __ldg((const float4*)&W3[c0 * 4]);
        float4 wr1 = __ldg((const float4*)&W3[(c0 + 1) * 4]);
        t0 = o2.x * wr0.x + o2.y * wr1.x;
        t1 = o2.x * wr0.y + o2.y * wr1.y;
        t2 = o2.x * wr0.z + o2.y * wr1.z;
        t3 = o2.x * wr0.w + o2.y * wr1.w;
    }
    #pragma unroll
    for (int o = 16; o; o >>= 1) {
        t0 += __shfl_xor_sync(0xffffffffu, t0, o);
        t1 += __shfl_xor_sync(0xffffffffu, t1, o);
        t2 += __shfl_xor_sync(0xffffffffu, t2, o);
        t3 += __shfl_xor_sync(0xffffffffu, t3, o);
    }
    if (lane == 0) {
        *(float4*)&h3out[(size_t)n * 4] = make_float4(t0, t1, t2, t3);
        g_als3[n] = t0 * __ldg(&as3[0]) + t1 * __ldg(&as3[1]) + t2 * __ldg(&as3[2]) + t3 * __ldg(&as3[3]);
        g_ald3[n] = t0 * __ldg(&ad3[0]) + t1 * __ldg(&ad3[1]) + t2 * __ldg(&ad3[2]) + t3 * __ldg(&ad3[3]);
    }
}

// ---------------- 7: layer-3 agg + global max pool ----------------
__global__ void k_agg3(const float* __restrict__ hfeat,
                       const float* __restrict__ bias,
                       const void* __restrict__ batch) {
    int wid = (blockIdx.x * blockDim.x + threadIdx.x) >> 5;
    if (wid >= NN) return;
    int lane = threadIdx.x & 31;
    int sub = lane >> 2, c = lane & 3;
    int n = wid;
    int beg = g_rowptr[n], end = g_rowptr[n + 1];
    float aldn = g_ald3[n];
    float acc = 0.f, wsum = 0.f;
    for (int e0 = beg; e0 < end; e0 += 8) {
        int e = e0 + sub;
        if (e < end) {
            int s = g_col[e];
            float al = g_als3[s] + aldn;
            al = (al > 0.f) ? al : 0.2f * al;
            float w = __expf(fminf(al, 80.f));
            acc += w * __ldg(&hfeat[(size_t)s * 4 + c]);
            wsum += w;
        }
    }
    #pragma unroll
    for (int o = 4; o < 32; o <<= 1) {
        acc += __shfl_xor_sync(0xffffffffu, acc, o);
        wsum += __shfl_xor_sync(0xffffffffu, wsum, o);
    }
    if (lane < 4) {
        float o = acc / (wsum + 1e-16f) + __ldg(&bias[lane]);
        bool is64 = (g_nz == 0);
        int g = (int)ld_idx(batch, n, is64);
        atomicMax(&g_pool[g * 4 + lane], enc(o));
    }
}

// ---------------- 8: log-softmax + restore clean state ----------------
__global__ void k_final(float* __restrict__ out) {
    int b = blockIdx.x, t = threadIdx.x;
    if (b == 0) {
        float v[4];
        #pragma unroll
        for (int c = 0; c < 4; c++) {
            unsigned u = g_pool[t * 4 + c];
            v[c] = (u <= 0x007FFFFFu) ? -1e9f : dec(u);
        }
        float m = fmaxf(fmaxf(v[0], v[1]), fmaxf(v[2], v[3]));
        float s = 0.f;
        #pragma unroll
        for (int c = 0; c < 4; c++) s += expf(v[c] - m);
        float lse = m + logf(s);
        #pragma unroll
        for (int c = 0; c < 4; c++) out[t * 4 + c] = v[c] - lse;
        __syncthreads();
        #pragma unroll
        for (int c = 0; c < 4; c++) g_pool[t * 4 + c] = 0u;
    }
    if (b == 1 && t == 0) { g_tick = 0; g_flag = 0; }
    int i = b * 256 + t;
    if (i < NN) g_deg[i] = 0;
}

// ---------------- launch ----------------
extern "C" void kernel_launch(void* const* d_in, const int* in_sizes, int n_in,
                              void* d_out, int out_size) {
    const float* x   = (const float*)d_in[0];
    const void*  ei  = d_in[1];
    const void*  bat = d_in[2];
    const float* W1  = (const float*)d_in[3];
    const float* as1 = (const float*)d_in[4];
    const float* ad1 = (const float*)d_in[5];
    const float* b1  = (const float*)d_in[6];
    const float* W2  = (const float*)d_in[7];
    const float* as2 = (const float*)d_in[8];
    const float* ad2 = (const float*)d_in[9];
    const float* b2  = (const float*)d_in[10];
    const float* W3  = (const float*)d_in[11];
    const float* as3 = (const float*)d_in[12];
    const float* ad3 = (const float*)d_in[13];
    const float* b3  = (const float*)d_in[14];
    float* out = (float*)d_out;

    float *hbuf, *obuf;
    cudaGetSymbolAddress((void**)&hbuf, g_h);
    cudaGetSymbolAddress((void**)&obuf, g_o);

    k_alpha_x<<<(NN + 255) / 256, 256>>>(x, W1, as1, ad1, W2, (const int*)ei);  // 1
    k_count<<<(NE + 255) / 256, 256>>>(ei);                                     // 2
    k_scanall<<<NB5, 512>>>();                                                  // 3
    k_fill<<<(NET + 255) / 256, 256>>>(ei);                                     // 4
    k_gemmA<<<NN / 64, 256>>>(x, W1, b1, hbuf, as2, ad2);                       // 5
    k_agg2<<<NN / 8, 256>>>(hbuf, b2, W3, as3, ad3, obuf);                      // 6
    k_agg3<<<NN / 8, 256>>>(obuf, b3, bat);                                     // 7
    k_final<<<(NN + 255) / 256, 256>>>(out);                                    // 8
}

// round 13
// speedup vs baseline: 1.0363x; 1.0363x over previous
#include <cuda_runtime.h>
#include <math.h>

#define NN 80000
#define NE 1280000
#define NET (NE + NN)
#define NGR 256
#define NB5 157          // ceil(NN/512)
#define KP 136
#define WPAD 56

// ---------------- static device scratch (zero at entry, restored at exit) ----------------
__device__ int g_deg[NN];          // ZERO at entry (restored by k_final)
__device__ int g_rowptr[NN + 1];
__device__ int g_cursor[NN];
__device__ int g_col[NET];
__device__ int g_bsum[NB5];
__device__ int g_boff[NB5];
__device__ int g_tick;             // ZERO at entry
__device__ int g_flag;             // ZERO at entry
__device__ float g_h[(size_t)NN * 54];
__device__ float g_o[(size_t)NN * 4];
__device__ float g_xagg[(size_t)NN * 27];
__device__ float g_W2p[KP * WPAD];
__device__ float g_als3[NN];
__device__ float g_ald3[NN];
__device__ float4 g_als[NN];       // layer-1 logits
__device__ float4 g_ald[NN];
__device__ float4 g_als2[NN];      // layer-2 logits (separate: no cross-kernel WAR)
__device__ float4 g_ald2[NN];
__device__ unsigned g_pool[NGR * 4];  // ZERO at entry (0 < enc(-inf))
__device__ int g_nz;

__device__ __forceinline__ unsigned enc(float f) {
    unsigned u = __float_as_uint(f);
    return (u & 0x80000000u) ? ~u : (u | 0x80000000u);
}
__device__ __forceinline__ float dec(unsigned u) {
    return __uint_as_float((u & 0x80000000u) ? (u ^ 0x80000000u) : ~u);
}
__device__ __forceinline__ long long ld_idx(const void* p, long long i, bool is64) {
    if (is64) return ((const long long*)p)[i];
    return (long long)((const int*)p)[i];
}

// ---------------- 1: layer-1 logits + W2 pad + dtype sniff + rowptr[NN] ----------------
__global__ void k_alpha_x(const float* __restrict__ x, const float* __restrict__ W1,
                          const float* __restrict__ a_src, const float* __restrict__ a_dst,
                          const float* __restrict__ W2, const int* ei32) {
    __shared__ float v[2][3][9];
    int t = threadIdx.x;
    int gi = blockIdx.x * blockDim.x + t;
    if (gi < KP * WPAD) {
        int k = gi / WPAD, c = gi - k * WPAD;
        g_W2p[gi] = (k < 135 && c < 54) ? W2[k * 54 + c] : 0.f;
    }
    if (gi == 0) g_rowptr[NN] = NET;
    if (blockIdx.x == 0 && t < 32) {
        int nz = 0;
        for (int j = t; j < 512; j += 32)
            if (ei32[2 * j + 1] != 0) nz++;
        #pragma unroll
        for (int o = 16; o; o >>= 1) nz += __shfl_xor_sync(0xffffffffu, nz, o);
        if (t == 0) g_nz = nz;   // 0 => int64
    }
    if (t < 54) {
        int side = t / 27, r = t % 27;
        int h = r / 9, k = r % 9;
        const float* a = side ? a_dst : a_src;
        float s = 0.f;
        for (int c = 0; c < 45; c++)
            s += __ldg(&W1[k * 135 + h * 45 + c]) * __ldg(&a[h * 45 + c]);
        v[side][h][k] = s;
    }
    __syncthreads();
    int n = gi;
    if (n >= NN) return;
    float xv[9];
    #pragma unroll
    for (int k = 0; k < 9; k++) xv[k] = x[(size_t)n * 9 + k];
    float s[3], d[3];
    #pragma unroll
    for (int h = 0; h < 3; h++) {
        float ss = 0.f, dd = 0.f;
        #pragma unroll
        for (int k = 0; k < 9; k++) {
            ss += xv[k] * v[0][h][k];
            dd += xv[k] * v[1][h][k];
        }
        s[h] = ss; d[h] = dd;
    }
    g_als[n] = make_float4(s[0], s[1], s[2], 0.f);
    g_ald[n] = make_float4(d[0], d[1], d[2], 0.f);
}

// ---------------- 2: degree count ----------------
__global__ void k_count(const void* ei) {
    int e = blockIdx.x * blockDim.x + threadIdx.x;
    if (e >= NE) return;
    bool is64 = (g_nz == 0);
    int dst = (int)ld_idx(ei, (long long)NE + e, is64);
    atomicAdd(&g_deg[dst], 1);
}

// ---------------- 3: single-pass exclusive scan of (deg+1) ----------------
__global__ void k_scanall() {
    __shared__ int sm[512];
    __shared__ int s_last;
    __shared__ int s_off;
    int b = blockIdx.x, t = threadIdx.x;
    int i = b * 512 + t;
    int v = (i < NN) ? g_deg[i] + 1 : 0;   // +1 = self loop
    sm[t] = v;
    __syncthreads();
    #pragma unroll
    for (int off = 1; off < 512; off <<= 1) {
        int u = (t >= off) ? sm[t - off] : 0;
        __syncthreads();
        sm[t] += u;
        __syncthreads();
    }
    int incl = sm[t];
    int total = sm[511];
    __syncthreads();
    if (t == 0) {
        g_bsum[b] = total;
        __threadfence();
        int tk = atomicAdd(&g_tick, 1);
        s_last = (tk == NB5 - 1);
    }
    __syncthreads();
    if (s_last) {
        int u = (t < NB5) ? g_bsum[t] : 0;
        sm[t] = u;
        __syncthreads();
        #pragma unroll
        for (int off = 1; off < 512; off <<= 1) {
            int w = (t >= off) ? sm[t - off] : 0;
            __syncthreads();
            sm[t] += w;
            __syncthreads();
        }
        if (t < NB5) g_boff[t] = sm[t] - u;   // exclusive
        __threadfence();
        if (t == 0) atomicExch(&g_flag, 1);
    } else {
        if (t == 0) {
            while (atomicAdd(&g_flag, 0) == 0) __nanosleep(64);
        }
    }
    __syncthreads();
    if (t == 0) s_off = atomicAdd(&g_boff[b], 0);
    __syncthreads();
    if (i < NN) {
        int p = s_off + incl - v;
        g_rowptr[i] = p;
        g_cursor[i] = p;
    }
}

// ---------------- 4: CSR fill ----------------
__global__ void k_fill(const void* ei) {
    int e = blockIdx.x * blockDim.x + threadIdx.x;
    if (e >= NET) return;
    bool is64 = (g_nz == 0);
    int s, d;
    if (e < NE) {
        s = (int)ld_idx(ei, e, is64);
        d = (int)ld_idx(ei, (long long)NE + e, is64);
    } else {
        s = d = e - NE;
    }
    int pos = atomicAdd(&g_cursor[d], 1);
    g_col[pos] = s;
}

// ---------------- 5: layer-1 aggregation of raw x, warp/node ----------------
__global__ void k_aggx(const float* __restrict__ x) {
    int wid = (blockIdx.x * blockDim.x + threadIdx.x) >> 5;
    if (wid >= NN) return;
    int lane = threadIdx.x & 31;
    int n = wid;
    int hh = lane / 9, cc = lane - hh * 9;
    bool act = lane < 27;
    int beg = g_rowptr[n], end = g_rowptr[n + 1];
    float4 ald4 = g_ald[n];
    float aldv[3] = { ald4.x, ald4.y, ald4.z };
    float acc = 0.f;
    float ssum[3] = { 0.f, 0.f, 0.f };

    for (int base = beg; base < end; base += 32) {
        int cnt = min(32, end - base);
        int s_l = 0;
        float e_l[3] = { 0.f, 0.f, 0.f };
        if (lane < cnt) {
            s_l = g_col[base + lane];
            float4 a = g_als[s_l];
            float av[3] = { a.x, a.y, a.z };
            #pragma unroll
            for (int h = 0; h < 3; h++) {
                float al = av[h] + aldv[h];
                al = (al > 0.f) ? al : 0.2f * al;
                e_l[h] = __expf(fminf(al, 80.f));
            }
        }
        #pragma unroll
        for (int h = 0; h < 3; h++) ssum[h] += e_l[h];

        int jj = 0;
        for (; jj + 4 <= cnt; jj += 4) {
            int s0 = __shfl_sync(0xffffffffu, s_l, jj + 0);
            int s1 = __shfl_sync(0xffffffffu, s_l, jj + 1);
            int s2 = __shfl_sync(0xffffffffu, s_l, jj + 2);
            int s3 = __shfl_sync(0xffffffffu, s_l, jj + 3);
            float w0a = __shfl_sync(0xffffffffu, e_l[0], jj + 0);
            float w0b = __shfl_sync(0xffffffffu, e_l[1], jj + 0);
            float w0c = __shfl_sync(0xffffffffu, e_l[2], jj + 0);
            float w1a = __shfl_sync(0xffffffffu, e_l[0], jj + 1);
            float w1b = __shfl_sync(0xffffffffu, e_l[1], jj + 1);
            float w1c = __shfl_sync(0xffffffffu, e_l[2], jj + 1);
            float w2a = __shfl_sync(0xffffffffu, e_l[0], jj + 2);
            float w2b = __shfl_sync(0xffffffffu, e_l[1], jj + 2);
            float w2c = __shfl_sync(0xffffffffu, e_l[2], jj + 2);
            float w3a = __shfl_sync(0xffffffffu, e_l[0], jj + 3);
            float w3b = __shfl_sync(0xffffffffu, e_l[1], jj + 3);
            float w3c = __shfl_sync(0xffffffffu, e_l[2], jj + 3);
            if (act) {
                float x0 = __ldg(&x[(size_t)s0 * 9 + cc]);
                float x1 = __ldg(&x[(size_t)s1 * 9 + cc]);
                float x2 = __ldg(&x[(size_t)s2 * 9 + cc]);
                float x3 = __ldg(&x[(size_t)s3 * 9 + cc]);
                float wa = (hh == 0) ? w0a : (hh == 1) ? w0b : w0c;
                float wb = (hh == 0) ? w1a : (hh == 1) ? w1b : w1c;
                float wc = (hh == 0) ? w2a : (hh == 1) ? w2b : w2c;
                float wd = (hh == 0) ? w3a : (hh == 1) ? w3b : w3c;
                acc += wa * x0;
                acc += wb * x1;
                acc += wc * x2;
                acc += wd * x3;
            }
        }
        for (; jj < cnt; jj++) {
            int s = __shfl_sync(0xffffffffu, s_l, jj);
            float wa0 = __shfl_sync(0xffffffffu, e_l[0], jj);
            float wa1 = __shfl_sync(0xffffffffu, e_l[1], jj);
            float wa2 = __shfl_sync(0xffffffffu, e_l[2], jj);
            if (act) {
                float xv = __ldg(&x[(size_t)s * 9 + cc]);
                float w = (hh == 0) ? wa0 : (hh == 1) ? wa1 : wa2;
                acc += w * xv;
            }
        }
    }
    #pragma unroll
    for (int h = 0; h < 3; h++)
        #pragma unroll
        for (int o = 16; o; o >>= 1)
            ssum[h] += __shfl_xor_sync(0xffffffffu, ssum[h], o);
    if (act)
        g_xagg[(size_t)n * 27 + lane] = acc / (ssum[hh] + 1e-16f);
}

// ---------------- 6: fused map1 + gemm2 + alpha2 (writes g_als2/g_ald2) ----------------
__global__ void k_gemm2f(const float* __restrict__ W1, const float* __restrict__ b1,
                         float* __restrict__ Y,
                         const float* __restrict__ a_src, const float* __restrict__ a_dst) {
    constexpr int NPB = 64;
    __shared__ __align__(16) float xs[NPB * KP];
    __shared__ float xa[NPB * 28];
    int tid = threadIdx.x;
    int nodeBase = blockIdx.x * NPB;
    for (int i = tid; i < NPB * 27; i += 256) {
        int r = i / 27, c = i - r * 27;
        xa[r * 28 + c] = g_xagg[(size_t)(nodeBase + r) * 27 + c];
    }
    __syncthreads();
    for (int i = tid; i < NPB * KP; i += 256) {
        int r = i / KP, c = i - r * KP;
        float o = 0.f;
        if (c < 135) {
            int h = c / 45;
            const float* ap = xa + r * 28 + h * 9;
            float s = 0.f;
            #pragma unroll
            for (int k = 0; k < 9; k++)
                s += ap[k] * __ldg(&W1[k * 135 + c]);
            o = fmaxf(s + __ldg(&b1[c]), 0.f);
        }
        xs[i] = o;
    }
    __syncthreads();
    int ng = tid / 16, j = tid & 15;
    int c0 = j * 4;
    float acc[4][4];
    #pragma unroll
    for (int q = 0; q < 4; q++)
        #pragma unroll
        for (int m = 0; m < 4; m++) acc[q][m] = 0.f;
    const float* xp = xs + (ng * 4) * KP;
    for (int k4 = 0; k4 < KP / 4; k4++) {
        float xr0[4], xr1[4], xr2[4], xr3[4];
        *(float4*)xr0 = *(const float4*)&xp[k4 * 4];
        *(float4*)xr1 = *(const float4*)&xp[KP + k4 * 4];
        *(float4*)xr2 = *(const float4*)&xp[2 * KP + k4 * 4];
        *(float4*)xr3 = *(const float4*)&xp[3 * KP + k4 * 4];
        #pragma unroll
        for (int kk = 0; kk < 4; kk++) {
            float wr[4];
            *(float4*)wr = __ldg((const float4*)&g_W2p[(k4 * 4 + kk) * WPAD + c0]);
            #pragma unroll
            for (int m = 0; m < 4; m++) {
                acc[0][m] += xr0[kk] * wr[m];
                acc[1][m] += xr1[kk] * wr[m];
                acc[2][m] += xr2[kk] * wr[m];
                acc[3][m] += xr3[kk] * wr[m];
            }
        }
    }
    float as_c[4], ad_c[4];
    #pragma unroll
    for (int m = 0; m < 4; m++) {
        int c = c0 + m;
        as_c[m] = (c < 54) ? __ldg(&a_src[c]) : 0.f;
        ad_c[m] = (c < 54) ? __ldg(&a_dst[c]) : 0.f;
    }
    #pragma unroll
    for (int q = 0; q < 4; q++) {
        int n = nodeBase + ng * 4 + q;
        float ps0 = 0.f, ps1 = 0.f, ps2 = 0.f;
        float pd0 = 0.f, pd1 = 0.f, pd2 = 0.f;
        #pragma unroll
        for (int m = 0; m < 4; m++) {
            int c = c0 + m;
            if (c < 54) {
                Y[(size_t)n * 54 + c] = acc[q][m];
                int h = c / 18;
                float vs = acc[q][m] * as_c[m];
                float vd = acc[q][m] * ad_c[m];
                if (h == 0) { ps0 += vs; pd0 += vd; }
                else if (h == 1) { ps1 += vs; pd1 += vd; }
                else { ps2 += vs; pd2 += vd; }
            }
        }
        #pragma unroll
        for (int o = 8; o; o >>= 1) {
            ps0 += __shfl_xor_sync(0xffffffffu, ps0, o);
            ps1 += __shfl_xor_sync(0xffffffffu, ps1, o);
            ps2 += __shfl_xor_sync(0xffffffffu, ps2, o);
            pd0 += __shfl_xor_sync(0xffffffffu, pd0, o);
            pd1 += __shfl_xor_sync(0xffffffffu, pd1, o);
            pd2 += __shfl_xor_sync(0xffffffffu, pd2, o);
        }
        if (j == 0) {
            g_als2[n] = make_float4(ps0, ps1, ps2, 0.f);
            g_ald2[n] = make_float4(pd0, pd1, pd2, 0.f);
        }
    }
}

// ---------------- 7: agg2 + fused gemm3 + layer-3 logits (reads g_als2/g_ald2) ----------------
__global__ void k_agg2(const float* __restrict__ hfeat,
                       const float* __restrict__ bias,
                       const float* __restrict__ W3,
                       const float* __restrict__ as3, const float* __restrict__ ad3,
                       float* __restrict__ h3out) {
    int wid = (blockIdx.x * blockDim.x + threadIdx.x) >> 5;
    if (wid >= NN) return;
    int lane = threadIdx.x & 31;
    int n = wid;
    bool act = lane < 27;
    int c0 = 2 * lane;
    int hd = lane / 9;
    int beg = g_rowptr[n], end = g_rowptr[n + 1];
    float4 ald4 = g_ald2[n];
    float aldv[3] = { ald4.x, ald4.y, ald4.z };
    float2 acc = make_float2(0.f, 0.f);
    float ssum0 = 0.f, ssum1 = 0.f, ssum2 = 0.f;

    for (int base = beg; base < end; base += 32) {
        int cnt = min(32, end - base);
        int s_l = 0;
        float e_l[3] = { 0.f, 0.f, 0.f };
        if (lane < cnt) {
            s_l = g_col[base + lane];
            float4 a = g_als2[s_l];
            float av[3] = { a.x, a.y, a.z };
            #pragma unroll
            for (int h = 0; h < 3; h++) {
                float al = av[h] + aldv[h];
                al = (al > 0.f) ? al : 0.2f * al;
                e_l[h] = __expf(fminf(al, 80.f));
            }
        }
        ssum0 += e_l[0]; ssum1 += e_l[1]; ssum2 += e_l[2];

        int jj = 0;
        for (; jj + 4 <= cnt; jj += 4) {
            int s0 = __shfl_sync(0xffffffffu, s_l, jj + 0);
            int s1 = __shfl_sync(0xffffffffu, s_l, jj + 1);
            int s2 = __shfl_sync(0xffffffffu, s_l, jj + 2);
            int s3 = __shfl_sync(0xffffffffu, s_l, jj + 3);
            float w0a = __shfl_sync(0xffffffffu, e_l[0], jj + 0);
            float w0b = __shfl_sync(0xffffffffu, e_l[1], jj + 0);
            float w0c = __shfl_sync(0xffffffffu, e_l[2], jj + 0);
            float w1a = __shfl_sync(0xffffffffu, e_l[0], jj + 1);
            float w1b = __shfl_sync(0xffffffffu, e_l[1], jj + 1);
            float w1c = __shfl_sync(0xffffffffu, e_l[2], jj + 1);
            float w2a = __shfl_sync(0xffffffffu, e_l[0], jj + 2);
            float w2b = __shfl_sync(0xffffffffu, e_l[1], jj + 2);
            float w2c = __shfl_sync(0xffffffffu, e_l[2], jj + 2);
            float w3a = __shfl_sync(0xffffffffu, e_l[0], jj + 3);
            float w3b = __shfl_sync(0xffffffffu, e_l[1], jj + 3);
            float w3c = __shfl_sync(0xffffffffu, e_l[2], jj + 3);
            if (act) {
                float2 g0 = *(const float2*)&hfeat[(size_t)s0 * 54 + c0];
                float2 g1 = *(const float2*)&hfeat[(size_t)s1 * 54 + c0];
                float2 g2 = *(const float2*)&hfeat[(size_t)s2 * 54 + c0];
                float2 g3 = *(const float2*)&hfeat[(size_t)s3 * 54 + c0];
                float wa = (hd == 0) ? w0a : (hd == 1) ? w0b : w0c;
                float wb = (hd == 0) ? w1a : (hd == 1) ? w1b : w1c;
                float wc = (hd == 0) ? w2a : (hd == 1) ? w2b : w2c;
                float wd = (hd == 0) ? w3a : (hd == 1) ? w3b : w3c;
                acc.x += wa * g0.x; acc.y += wa * g0.y;
                acc.x += wb * g1.x; acc.y += wb * g1.y;
                acc.x += wc * g2.x; acc.y += wc * g2.y;
                acc.x += wd * g3.x; acc.y += wd * g3.y;
            }
        }
        for (; jj < cnt; jj++) {
            int s = __shfl_sync(0xffffffffu, s_l, jj);
            float wa0 = __shfl_sync(0xffffffffu, e_l[0], jj);
            float wa1 = __shfl_sync(0xffffffffu, e_l[1], jj);
            float wa2 = __shfl_sync(0xffffffffu, e_l[2], jj);
            if (act) {
                float2 g = *(const float2*)&hfeat[(size_t)s * 54 + c0];
                float ww = (hd == 0) ? wa0 : (hd == 1) ? wa1 : wa2;
                acc.x += ww * g.x; acc.y += ww * g.y;
            }
        }
    }
    #pragma unroll
    for (int o = 16; o; o >>= 1) {
        ssum0 += __shfl_xor_sync(0xffffffffu, ssum0, o);
        ssum1 += __shfl_xor_sync(0xffffffffu, ssum1, o);
        ssum2 += __shfl_xor_sync(0xffffffffu, ssum2, o);
    }
    float2 o2 = make_float2(0.f, 0.f);
    if (act) {
        float ss = (hd == 0) ? ssum0 : (hd == 1) ? ssum1 : ssum2;
        float inv = 1.f / (ss + 1e-16f);
        o2.x = fmaxf(acc.x * inv + __ldg(&bias[c0]), 0.f);
        o2.y = fmaxf(acc.y * inv + __ldg(&bias[c0 + 1]), 0.f);
    }
    float t0 = 0.f, t1 = 0.f, t2 = 0.f, t3 = 0.f;
    if (act) {
        float4 wr0 = __ldg((const float4*)&W3[c0 * 4]);
        float4 wr1 = __ldg((const float4*)&W3[(c0 + 1) * 4]);
        t0 = o2.x * wr0.x + o2.y * wr1.x;
        t1 = o2.x * wr0.y + o2.y * wr1.y;
        t2 = o2.x * wr0.z + o2.y * wr1.z;
        t3 = o2.x * wr0.w + o2.y * wr1.w;
    }
    #pragma unroll
    for (int o = 16; o; o >>= 1) {
        t0 += __shfl_xor_sync(0xffffffffu, t0, o);
        t1 += __shfl_xor_sync(0xffffffffu, t1, o);
        t2 += __shfl_xor_sync(0xffffffffu, t2, o);
        t3 += __shfl_xor_sync(0xffffffffu, t3, o);
    }
    if (lane == 0) {
        *(float4*)&h3out[(size_t)n * 4] = make_float4(t0, t1, t2, t3);
        g_als3[n] = t0 * __ldg(&as3[0]) + t1 * __ldg(&as3[1]) + t2 * __ldg(&as3[2]) + t3 * __ldg(&as3[3]);
        g_ald3[n] = t0 * __ldg(&ad3[0]) + t1 * __ldg(&ad3[1]) + t2 * __ldg(&ad3[2]) + t3 * __ldg(&ad3[3]);
    }
}

// ---------------- 8: layer-3 agg + global max pool ----------------
__global__ void k_agg3(const float* __restrict__ hfeat,
                       const float* __restrict__ bias,
                       const void* __restrict__ batch) {
    int wid = (blockIdx.x * blockDim.x + threadIdx.x) >> 5;
    if (wid >= NN) return;
    int lane = threadIdx.x & 31;
    int sub = lane >> 2, c = lane & 3;
    int n = wid;
    int beg = g_rowptr[n], end = g_rowptr[n + 1];
    float aldn = g_ald3[n];
    float acc = 0.f, wsum = 0.f;
    for (int e0 = beg; e0 < end; e0 += 8) {
        int e = e0 + sub;
        if (e < end) {
            int s = g_col[e];
            float al = g_als3[s] + aldn;
            al = (al > 0.f) ? al : 0.2f * al;
            float w = __expf(fminf(al, 80.f));
            acc += w * __ldg(&hfeat[(size_t)s * 4 + c]);
            wsum += w;
        }
    }
    #pragma unroll
    for (int o = 4; o < 32; o <<= 1) {
        acc += __shfl_xor_sync(0xffffffffu, acc, o);
        wsum += __shfl_xor_sync(0xffffffffu, wsum, o);
    }
    if (lane < 4) {
        float o = acc / (wsum + 1e-16f) + __ldg(&bias[lane]);
        bool is64 = (g_nz == 0);
        int g = (int)ld_idx(batch, n, is64);
        atomicMax(&g_pool[g * 4 + lane], enc(o));
    }
}

// ---------------- 9: log-softmax + restore clean state ----------------
__global__ void k_final(float* __restrict__ out) {
    int b = blockIdx.x, t = threadIdx.x;
    if (b == 0) {
        float v[4];
        #pragma unroll
        for (int c = 0; c < 4; c++) {
            unsigned u = g_pool[t * 4 + c];
            v[c] = (u <= 0x007FFFFFu) ? -1e9f : dec(u);
        }
        float m = fmaxf(fmaxf(v[0], v[1]), fmaxf(v[2], v[3]));
        float s = 0.f;
        #pragma unroll
        for (int c = 0; c < 4; c++) s += expf(v[c] - m);
        float lse = m + logf(s);
        #pragma unroll
        for (int c = 0; c < 4; c++) out[t * 4 + c] = v[c] - lse;
        __syncthreads();
        #pragma unroll
        for (int c = 0; c < 4; c++) g_pool[t * 4 + c] = 0u;
    }
    if (b == 1 && t == 0) { g_tick = 0; g_flag = 0; }
    int i = b * 256 + t;
    if (i < NN) g_deg[i] = 0;
}

// ---------------- launch ----------------
extern "C" void kernel_launch(void* const* d_in, const int* in_sizes, int n_in,
                              void* d_out, int out_size) {
    const float* x   = (const float*)d_in[0];
    const void*  ei  = d_in[1];
    const void*  bat = d_in[2];
    const float* W1  = (const float*)d_in[3];
    const float* as1 = (const float*)d_in[4];
    const float* ad1 = (const float*)d_in[5];
    const float* b1  = (const float*)d_in[6];
    const float* W2  = (const float*)d_in[7];
    const float* as2 = (const float*)d_in[8];
    const float* ad2 = (const float*)d_in[9];
    const float* b2  = (const float*)d_in[10];
    const float* W3  = (const float*)d_in[11];
    const float* as3 = (const float*)d_in[12];
    const float* ad3 = (const float*)d_in[13];
    const float* b3  = (const float*)d_in[14];
    float* out = (float*)d_out;

    float *hbuf, *obuf;
    cudaGetSymbolAddress((void**)&hbuf, g_h);
    cudaGetSymbolAddress((void**)&obuf, g_o);

    k_alpha_x<<<(NN + 255) / 256, 256>>>(x, W1, as1, ad1, W2, (const int*)ei);  // 1
    k_count<<<(NE + 255) / 256, 256>>>(ei);                                     // 2
    k_scanall<<<NB5, 512>>>();                                                  // 3
    k_fill<<<(NET + 255) / 256, 256>>>(ei);                                     // 4
    k_aggx<<<NN / 8, 256>>>(x);                                                 // 5
    k_gemm2f<<<NN / 64, 256>>>(W1, b1, hbuf, as2, ad2);                         // 6
    k_agg2<<<NN / 8, 256>>>(hbuf, b2, W3, as3, ad3, obuf);                      // 7
    k_agg3<<<NN / 8, 256>>>(obuf, b3, bat);                                     // 8
    k_final<<<(NN + 255) / 256, 256>>>(out);                                    // 9
}

// round 15
// speedup vs baseline: 1.0564x; 1.0194x over previous
#include <cuda_runtime.h>
#include <math.h>

#define NN 80000
#define NE 1280000
#define NGR 256
#define KP 136
#define WPAD 56
#define SLOT 48
#define OVF_MAX 16384

// ---------------- static device scratch (zero at entry, restored at exit) ----------------
__device__ int g_cnt[NN];            // ZERO at entry (restored by k_final)
__device__ int g_ovf_cnt;            // ZERO at entry (restored by k_final)
__device__ int2 g_ovf[OVF_MAX];      // overflow (dst, src) pairs — normally empty
__device__ int g_slot[(size_t)NN * SLOT];
__device__ float g_h[(size_t)NN * 54];
__device__ float g_o[(size_t)NN * 4];
__device__ float g_xagg[(size_t)NN * 27];
__device__ float g_W2p[KP * WPAD];
__device__ float g_als3[NN];
__device__ float g_ald3[NN];
__device__ float4 g_als[NN];         // layer-1 logits
__device__ float4 g_ald[NN];
__device__ float4 g_als2[NN];        // layer-2 logits (separate buffers: no cross-kernel WAR)
__device__ float4 g_ald2[NN];
__device__ unsigned g_pool[NGR * 4]; // ZERO at entry (0 < enc(-inf))
__device__ int g_nz;

__device__ __forceinline__ unsigned enc(float f) {
    unsigned u = __float_as_uint(f);
    return (u & 0x80000000u) ? ~u : (u | 0x80000000u);
}
__device__ __forceinline__ float dec(unsigned u) {
    return __uint_as_float((u & 0x80000000u) ? (u ^ 0x80000000u) : ~u);
}
__device__ __forceinline__ long long ld_idx(const void* p, long long i, bool is64) {
    if (is64) return ((const long long*)p)[i];
    return (long long)((const int*)p)[i];
}
__device__ __forceinline__ float lrelu_exp(float al) {
    al = (al > 0.f) ? al : 0.2f * al;
    return __expf(fminf(al, 80.f));
}

// ---------------- 1: layer-1 logits + W2 pad + dtype sniff ----------------
__global__ void k_alpha_x(const float* __restrict__ x, const float* __restrict__ W1,
                          const float* __restrict__ a_src, const float* __restrict__ a_dst,
                          const float* __restrict__ W2, const int* ei32) {
    __shared__ float v[2][3][9];
    int t = threadIdx.x;
    int gi = blockIdx.x * blockDim.x + t;
    if (gi < KP * WPAD) {
        int k = gi / WPAD, c = gi - k * WPAD;
        g_W2p[gi] = (k < 135 && c < 54) ? W2[k * 54 + c] : 0.f;
    }
    if (blockIdx.x == 0 && t < 32) {
        int nz = 0;
        for (int j = t; j < 512; j += 32)
            if (ei32[2 * j + 1] != 0) nz++;
        #pragma unroll
        for (int o = 16; o; o >>= 1) nz += __shfl_xor_sync(0xffffffffu, nz, o);
        if (t == 0) g_nz = nz;   // 0 => int64
    }
    if (t < 54) {
        int side = t / 27, r = t % 27;
        int h = r / 9, k = r % 9;
        const float* a = side ? a_dst : a_src;
        float s = 0.f;
        for (int c = 0; c < 45; c++)
            s += __ldg(&W1[k * 135 + h * 45 + c]) * __ldg(&a[h * 45 + c]);
        v[side][h][k] = s;
    }
    __syncthreads();
    int n = gi;
    if (n >= NN) return;
    float xv[9];
    #pragma unroll
    for (int k = 0; k < 9; k++) xv[k] = x[(size_t)n * 9 + k];
    float s[3], d[3];
    #pragma unroll
    for (int h = 0; h < 3; h++) {
        float ss = 0.f, dd = 0.f;
        #pragma unroll
        for (int k = 0; k < 9; k++) {
            ss += xv[k] * v[0][h][k];
            dd += xv[k] * v[1][h][k];
        }
        s[h] = ss; d[h] = dd;
    }
    g_als[n] = make_float4(s[0], s[1], s[2], 0.f);
    g_ald[n] = make_float4(d[0], d[1], d[2], 0.f);
}

// ---------------- 2: slot-CSR fill (no count, no scan; self-loops implicit) ----------------
__global__ void k_fill(const void* ei) {
    int e = blockIdx.x * blockDim.x + threadIdx.x;
    if (e >= NE) return;
    bool is64 = (g_nz == 0);
    int s = (int)ld_idx(ei, e, is64);
    int d = (int)ld_idx(ei, (long long)NE + e, is64);
    int pos = atomicAdd(&g_cnt[d], 1);
    if (pos < SLOT) {
        g_slot[(size_t)d * SLOT + pos] = s;
    } else {
        int op = atomicAdd(&g_ovf_cnt, 1);
        if (op < OVF_MAX) g_ovf[op] = make_int2(d, s);
    }
}

// ---------------- 3: layer-1 aggregation of raw x, warp/node ----------------
__global__ void k_aggx(const float* __restrict__ x) {
    int wid = (blockIdx.x * blockDim.x + threadIdx.x) >> 5;
    if (wid >= NN) return;
    int lane = threadIdx.x & 31;
    int n = wid;
    int hh = lane / 9, cc = lane - hh * 9;
    bool act = lane < 27;
    int deg = g_cnt[n];
    int inslot = min(deg, SLOT);
    const int* slot = g_slot + (size_t)n * SLOT;
    float4 ald4 = g_ald[n];
    float aldv[3] = { ald4.x, ald4.y, ald4.z };
    float acc = 0.f;
    float ssum[3] = { 0.f, 0.f, 0.f };

    for (int base = 0; base < inslot; base += 32) {
        int cnt = min(32, inslot - base);
        int s_l = 0;
        float e_l[3] = { 0.f, 0.f, 0.f };
        if (lane < cnt) {
            s_l = slot[base + lane];
            float4 a = g_als[s_l];
            e_l[0] = lrelu_exp(a.x + aldv[0]);
            e_l[1] = lrelu_exp(a.y + aldv[1]);
            e_l[2] = lrelu_exp(a.z + aldv[2]);
        }
        #pragma unroll
        for (int h = 0; h < 3; h++) ssum[h] += e_l[h];

        int jj = 0;
        for (; jj + 4 <= cnt; jj += 4) {
            int s0 = __shfl_sync(0xffffffffu, s_l, jj + 0);
            int s1 = __shfl_sync(0xffffffffu, s_l, jj + 1);
            int s2 = __shfl_sync(0xffffffffu, s_l, jj + 2);
            int s3 = __shfl_sync(0xffffffffu, s_l, jj + 3);
            float w0a = __shfl_sync(0xffffffffu, e_l[0], jj + 0);
            float w0b = __shfl_sync(0xffffffffu, e_l[1], jj + 0);
            float w0c = __shfl_sync(0xffffffffu, e_l[2], jj + 0);
            float w1a = __shfl_sync(0xffffffffu, e_l[0], jj + 1);
            float w1b = __shfl_sync(0xffffffffu, e_l[1], jj + 1);
            float w1c = __shfl_sync(0xffffffffu, e_l[2], jj + 1);
            float w2a = __shfl_sync(0xffffffffu, e_l[0], jj + 2);
            float w2b = __shfl_sync(0xffffffffu, e_l[1], jj + 2);
            float w2c = __shfl_sync(0xffffffffu, e_l[2], jj + 2);
            float w3a = __shfl_sync(0xffffffffu, e_l[0], jj + 3);
            float w3b = __shfl_sync(0xffffffffu, e_l[1], jj + 3);
            float w3c = __shfl_sync(0xffffffffu, e_l[2], jj + 3);
            if (act) {
                float x0 = __ldg(&x[(size_t)s0 * 9 + cc]);
                float x1 = __ldg(&x[(size_t)s1 * 9 + cc]);
                float x2 = __ldg(&x[(size_t)s2 * 9 + cc]);
                float x3 = __ldg(&x[(size_t)s3 * 9 + cc]);
                float wa = (hh == 0) ? w0a : (hh == 1) ? w0b : w0c;
                float wb = (hh == 0) ? w1a : (hh == 1) ? w1b : w1c;
                float wc = (hh == 0) ? w2a : (hh == 1) ? w2b : w2c;
                float wd = (hh == 0) ? w3a : (hh == 1) ? w3b : w3c;
                acc += wa * x0;
                acc += wb * x1;
                acc += wc * x2;
                acc += wd * x3;
            }
        }
        for (; jj < cnt; jj++) {
            int s = __shfl_sync(0xffffffffu, s_l, jj);
            float wa0 = __shfl_sync(0xffffffffu, e_l[0], jj);
            float wa1 = __shfl_sync(0xffffffffu, e_l[1], jj);
            float wa2 = __shfl_sync(0xffffffffu, e_l[2], jj);
            if (act) {
                float xv = __ldg(&x[(size_t)s * 9 + cc]);
                float w = (hh == 0) ? wa0 : (hh == 1) ? wa1 : wa2;
                acc += w * xv;
            }
        }
    }
    #pragma unroll
    for (int h = 0; h < 3; h++)
        #pragma unroll
        for (int o = 16; o; o >>= 1)
            ssum[h] += __shfl_xor_sync(0xffffffffu, ssum[h], o);

    // overflow edges (normally none): uniform processing after reduction
    if (deg > SLOT) {
        int on = min(g_ovf_cnt, OVF_MAX);
        for (int i = 0; i < on; i++) {
            int2 p = g_ovf[i];
            if (p.x == n) {
                float4 a = g_als[p.y];
                float e0 = lrelu_exp(a.x + aldv[0]);
                float e1 = lrelu_exp(a.y + aldv[1]);
                float e2 = lrelu_exp(a.z + aldv[2]);
                ssum[0] += e0; ssum[1] += e1; ssum[2] += e2;
                if (act) {
                    float xv = __ldg(&x[(size_t)p.y * 9 + cc]);
                    float w = (hh == 0) ? e0 : (hh == 1) ? e1 : e2;
                    acc += w * xv;
                }
            }
        }
    }
    // implicit self-loop (uniform)
    {
        float4 a = g_als[n];
        float e0 = lrelu_exp(a.x + aldv[0]);
        float e1 = lrelu_exp(a.y + aldv[1]);
        float e2 = lrelu_exp(a.z + aldv[2]);
        ssum[0] += e0; ssum[1] += e1; ssum[2] += e2;
        if (act) {
            float xv = __ldg(&x[(size_t)n * 9 + cc]);
            float w = (hh == 0) ? e0 : (hh == 1) ? e1 : e2;
            acc += w * xv;
        }
    }
    if (act)
        g_xagg[(size_t)n * 27 + lane] = acc / (ssum[hh] + 1e-16f);
}

// ---------------- 4: fused map1 + gemm2 + alpha2 (writes g_als2/g_ald2) ----------------
__global__ void k_gemm2f(const float* __restrict__ W1, const float* __restrict__ b1,
                         float* __restrict__ Y,
                         const float* __restrict__ a_src, const float* __restrict__ a_dst) {
    constexpr int NPB = 64;
    __shared__ __align__(16) float xs[NPB * KP];
    __shared__ float xa[NPB * 28];
    int tid = threadIdx.x;
    int nodeBase = blockIdx.x * NPB;
    for (int i = tid; i < NPB * 27; i += 256) {
        int r = i / 27, c = i - r * 27;
        xa[r * 28 + c] = g_xagg[(size_t)(nodeBase + r) * 27 + c];
    }
    __syncthreads();
    for (int i = tid; i < NPB * KP; i += 256) {
        int r = i / KP, c = i - r * KP;
        float o = 0.f;
        if (c < 135) {
            int h = c / 45;
            const float* ap = xa + r * 28 + h * 9;
            float s = 0.f;
            #pragma unroll
            for (int k = 0; k < 9; k++)
                s += ap[k] * __ldg(&W1[k * 135 + c]);
            o = fmaxf(s + __ldg(&b1[c]), 0.f);
        }
        xs[i] = o;
    }
    __syncthreads();
    int ng = tid / 16, j = tid & 15;
    int c0 = j * 4;
    float acc[4][4];
    #pragma unroll
    for (int q = 0; q < 4; q++)
        #pragma unroll
        for (int m = 0; m < 4; m++) acc[q][m] = 0.f;
    const float* xp = xs + (ng * 4) * KP;
    for (int k4 = 0; k4 < KP / 4; k4++) {
        float xr0[4], xr1[4], xr2[4], xr3[4];
        *(float4*)xr0 = *(const float4*)&xp[k4 * 4];
        *(float4*)xr1 = *(const float4*)&xp[KP + k4 * 4];
        *(float4*)xr2 = *(const float4*)&xp[2 * KP + k4 * 4];
        *(float4*)xr3 = *(const float4*)&xp[3 * KP + k4 * 4];
        #pragma unroll
        for (int kk = 0; kk < 4; kk++) {
            float wr[4];
            *(float4*)wr = __ldg((const float4*)&g_W2p[(k4 * 4 + kk) * WPAD + c0]);
            #pragma unroll
            for (int m = 0; m < 4; m++) {
                acc[0][m] += xr0[kk] * wr[m];
                acc[1][m] += xr1[kk] * wr[m];
                acc[2][m] += xr2[kk] * wr[m];
                acc[3][m] += xr3[kk] * wr[m];
            }
        }
    }
    float as_c[4], ad_c[4];
    #pragma unroll
    for (int m = 0; m < 4; m++) {
        int c = c0 + m;
        as_c[m] = (c < 54) ? __ldg(&a_src[c]) : 0.f;
        ad_c[m] = (c < 54) ? __ldg(&a_dst[c]) : 0.f;
    }
    #pragma unroll
    for (int q = 0; q < 4; q++) {
        int n = nodeBase + ng * 4 + q;
        float ps0 = 0.f, ps1 = 0.f, ps2 = 0.f;
        float pd0 = 0.f, pd1 = 0.f, pd2 = 0.f;
        #pragma unroll
        for (int m = 0; m < 4; m++) {
            int c = c0 + m;
            if (c < 54) {
                Y[(size_t)n * 54 + c] = acc[q][m];
                int h = c / 18;
                float vs = acc[q][m] * as_c[m];
                float vd = acc[q][m] * ad_c[m];
                if (h == 0) { ps0 += vs; pd0 += vd; }
                else if (h == 1) { ps1 += vs; pd1 += vd; }
                else { ps2 += vs; pd2 += vd; }
            }
        }
        #pragma unroll
        for (int o = 8; o; o >>= 1) {
            ps0 += __shfl_xor_sync(0xffffffffu, ps0, o);
            ps1 += __shfl_xor_sync(0xffffffffu, ps1, o);
            ps2 += __shfl_xor_sync(0xffffffffu, ps2, o);
            pd0 += __shfl_xor_sync(0xffffffffu, pd0, o);
            pd1 += __shfl_xor_sync(0xffffffffu, pd1, o);
            pd2 += __shfl_xor_sync(0xffffffffu, pd2, o);
        }
        if (j == 0) {
            g_als2[n] = make_float4(ps0, ps1, ps2, 0.f);
            g_ald2[n] = make_float4(pd0, pd1, pd2, 0.f);
        }
    }
}

// ---------------- 5: agg2 + fused gemm3 + layer-3 logits ----------------
__global__ void k_agg2(const float* __restrict__ hfeat,
                       const float* __restrict__ bias,
                       const float* __restrict__ W3,
                       const float* __restrict__ as3, const float* __restrict__ ad3,
                       float* __restrict__ h3out) {
    int wid = (blockIdx.x * blockDim.x + threadIdx.x) >> 5;
    if (wid >= NN) return;
    int lane = threadIdx.x & 31;
    int n = wid;
    bool act = lane < 27;
    int c0 = 2 * lane;
    int hd = lane / 9;
    int deg = g_cnt[n];
    int inslot = min(deg, SLOT);
    const int* slot = g_slot + (size_t)n * SLOT;
    float4 ald4 = g_ald2[n];
    float aldv[3] = { ald4.x, ald4.y, ald4.z };
    float2 acc = make_float2(0.f, 0.f);
    float ssum0 = 0.f, ssum1 = 0.f, ssum2 = 0.f;

    for (int base = 0; base < inslot; base += 32) {
        int cnt = min(32, inslot - base);
        int s_l = 0;
        float e_l[3] = { 0.f, 0.f, 0.f };
        if (lane < cnt) {
            s_l = slot[base + lane];
            float4 a = g_als2[s_l];
            e_l[0] = lrelu_exp(a.x + aldv[0]);
            e_l[1] = lrelu_exp(a.y + aldv[1]);
            e_l[2] = lrelu_exp(a.z + aldv[2]);
        }
        ssum0 += e_l[0]; ssum1 += e_l[1]; ssum2 += e_l[2];

        int jj = 0;
        for (; jj + 4 <= cnt; jj += 4) {
            int s0 = __shfl_sync(0xffffffffu, s_l, jj + 0);
            int s1 = __shfl_sync(0xffffffffu, s_l, jj + 1);
            int s2 = __shfl_sync(0xffffffffu, s_l, jj + 2);
            int s3 = __shfl_sync(0xffffffffu, s_l, jj + 3);
            float w0a = __shfl_sync(0xffffffffu, e_l[0], jj + 0);
            float w0b = __shfl_sync(0xffffffffu, e_l[1], jj + 0);
            float w0c = __shfl_sync(0xffffffffu, e_l[2], jj + 0);
            float w1a = __shfl_sync(0xffffffffu, e_l[0], jj + 1);
            float w1b = __shfl_sync(0xffffffffu, e_l[1], jj + 1);
            float w1c = __shfl_sync(0xffffffffu, e_l[2], jj + 1);
            float w2a = __shfl_sync(0xffffffffu, e_l[0], jj + 2);
            float w2b = __shfl_sync(0xffffffffu, e_l[1], jj + 2);
            float w2c = __shfl_sync(0xffffffffu, e_l[2], jj + 2);
            float w3a = __shfl_sync(0xffffffffu, e_l[0], jj + 3);
            float w3b = __shfl_sync(0xffffffffu, e_l[1], jj + 3);
            float w3c = __shfl_sync(0xffffffffu, e_l[2], jj + 3);
            if (act) {
                float2 g0 = *(const float2*)&hfeat[(size_t)s0 * 54 + c0];
                float2 g1 = *(const float2*)&hfeat[(size_t)s1 * 54 + c0];
                float2 g2 = *(const float2*)&hfeat[(size_t)s2 * 54 + c0];
                float2 g3 = *(const float2*)&hfeat[(size_t)s3 * 54 + c0];
                float wa = (hd == 0) ? w0a : (hd == 1) ? w0b : w0c;
                float wb = (hd == 0) ? w1a : (hd == 1) ? w1b : w1c;
                float wc = (hd == 0) ? w2a : (hd == 1) ? w2b : w2c;
                float wd = (hd == 0) ? w3a : (hd == 1) ? w3b : w3c;
                acc.x += wa * g0.x; acc.y += wa * g0.y;
                acc.x += wb * g1.x; acc.y += wb * g1.y;
                acc.x += wc * g2.x; acc.y += wc * g2.y;
                acc.x += wd * g3.x; acc.y += wd * g3.y;
            }
        }
        for (; jj < cnt; jj++) {
            int s = __shfl_sync(0xffffffffu, s_l, jj);
            float wa0 = __shfl_sync(0xffffffffu, e_l[0], jj);
            float wa1 = __shfl_sync(0xffffffffu, e_l[1], jj);
            float wa2 = __shfl_sync(0xffffffffu, e_l[2], jj);
            if (act) {
                float2 g = *(const float2*)&hfeat[(size_t)s * 54 + c0];
                float ww = (hd == 0) ? wa0 : (hd == 1) ? wa1 : wa2;
                acc.x += ww * g.x; acc.y += ww * g.y;
            }
        }
    }
    #pragma unroll
    for (int o = 16; o; o >>= 1) {
        ssum0 += __shfl_xor_sync(0xffffffffu, ssum0, o);
        ssum1 += __shfl_xor_sync(0xffffffffu, ssum1, o);
        ssum2 += __shfl_xor_sync(0xffffffffu, ssum2, o);
    }
    // overflow edges (normally none)
    if (deg > SLOT) {
        int on = min(g_ovf_cnt, OVF_MAX);
        for (int i = 0; i < on; i++) {
            int2 p = g_ovf[i];
            if (p.x == n) {
                float4 a = g_als2[p.y];
                float e0 = lrelu_exp(a.x + aldv[0]);
                float e1 = lrelu_exp(a.y + aldv[1]);
                float e2 = lrelu_exp(a.z + aldv[2]);
                ssum0 += e0; ssum1 += e1; ssum2 += e2;
                if (act) {
                    float2 g = *(const float2*)&hfeat[(size_t)p.y * 54 + c0];
                    float ww = (hd == 0) ? e0 : (hd == 1) ? e1 : e2;
                    acc.x += ww * g.x; acc.y += ww * g.y;
                }
            }
        }
    }
    // implicit self-loop (uniform)
    {
        float4 a = g_als2[n];
        float e0 = lrelu_exp(a.x + aldv[0]);
        float e1 = lrelu_exp(a.y + aldv[1]);
        float e2 = lrelu_exp(a.z + aldv[2]);
        ssum0 += e0; ssum1 += e1; ssum2 += e2;
        if (act) {
            float2 g = *(const float2*)&hfeat[(size_t)n * 54 + c0];
            float ww = (hd == 0) ? e0 : (hd == 1) ? e1 : e2;
            acc.x += ww * g.x; acc.y += ww * g.y;
        }
    }
    float2 o2 = make_float2(0.f, 0.f);
    if (act) {
        float ss = (hd == 0) ? ssum0 : (hd == 1) ? ssum1 : ssum2;
        float inv = 1.f / (ss + 1e-16f);
        o2.x = fmaxf(acc.x * inv + __ldg(&bias[c0]), 0.f);
        o2.y = fmaxf(acc.y * inv + __ldg(&bias[c0 + 1]), 0.f);
    }
    float t0 = 0.f, t1 = 0.f, t2 = 0.f, t3 = 0.f;
    if (act) {
        float4 wr0 = __ldg((const float4*)&W3[c0 * 4]);
        float4 wr1 = __ldg((const float4*)&W3[(c0 + 1) * 4]);
        t0 = o2.x * wr0.x + o2.y * wr1.x;
        t1 = o2.x * wr0.y + o2.y * wr1.y;
        t2 = o2.x * wr0.z + o2.y * wr1.z;
        t3 = o2.x * wr0.w + o2.y * wr1.w;
    }
    #pragma unroll
    for (int o = 16; o; o >>= 1) {
        t0 += __shfl_xor_sync(0xffffffffu, t0, o);
        t1 += __shfl_xor_sync(0xffffffffu, t1, o);
        t2 += __shfl_xor_sync(0xffffffffu, t2, o);
        t3 += __shfl_xor_sync(0xffffffffu, t3, o);
    }
    if (lane == 0) {
        *(float4*)&h3out[(size_t)n * 4] = make_float4(t0, t1, t2, t3);
        g_als3[n] = t0 * __ldg(&as3[0]) + t1 * __ldg(&as3[1]) + t2 * __ldg(&as3[2]) + t3 * __ldg(&as3[3]);
        g_ald3[n] = t0 * __ldg(&ad3[0]) + t1 * __ldg(&ad3[1]) + t2 * __ldg(&ad3[2]) + t3 * __ldg(&ad3[3]);
    }
}

// ---------------- 6: layer-3 agg + global max pool ----------------
__global__ void k_agg3(const float* __restrict__ hfeat,
                       const float* __restrict__ bias,
                       const void* __restrict__ batch) {
    int wid = (blockIdx.x * blockDim.x + threadIdx.x) >> 5;
    if (wid >= NN) return;
    int lane = threadIdx.x & 31;
    int sub = lane >> 2, c = lane & 3;
    int n = wid;
    int deg = g_cnt[n];
    int inslot = min(deg, SLOT);
    const int* slot = g_slot + (size_t)n * SLOT;
    float aldn = g_ald3[n];
    float acc = 0.f, wsum = 0.f;
    for (int e0 = 0; e0 < inslot; e0 += 8) {
        int e = e0 + sub;
        if (e < inslot) {
            int s = slot[e];
            float w = lrelu_exp(g_als3[s] + aldn);
            acc += w * __ldg(&hfeat[(size_t)s * 4 + c]);
            wsum += w;
        }
    }
    #pragma unroll
    for (int o = 4; o < 32; o <<= 1) {
        acc += __shfl_xor_sync(0xffffffffu, acc, o);
        wsum += __shfl_xor_sync(0xffffffffu, wsum, o);
    }
    // overflow edges (normally none)
    if (deg > SLOT) {
        int on = min(g_ovf_cnt, OVF_MAX);
        for (int i = 0; i < on; i++) {
            int2 p = g_ovf[i];
            if (p.x == n) {
                float w = lrelu_exp(g_als3[p.y] + aldn);
                acc += w * __ldg(&hfeat[(size_t)p.y * 4 + c]);
                wsum += w;
            }
        }
    }
    // implicit self-loop (uniform per channel)
    {
        float w = lrelu_exp(g_als3[n] + aldn);
        acc += w * __ldg(&hfeat[(size_t)n * 4 + c]);
        wsum += w;
    }
    if (lane < 4) {
        float o = acc / (wsum + 1e-16f) + __ldg(&bias[lane]);
        bool is64 = (g_nz == 0);
        int g = (int)ld_idx(batch, n, is64);
        atomicMax(&g_pool[g * 4 + lane], enc(o));
    }
}

// ---------------- 7: log-softmax + restore clean state ----------------
__global__ void k_final(float* __restrict__ out) {
    int b = blockIdx.x, t = threadIdx.x;
    if (b == 0) {
        float v[4];
        #pragma unroll
        for (int c = 0; c < 4; c++) {
            unsigned u = g_pool[t * 4 + c];
            v[c] = (u <= 0x007FFFFFu) ? -1e9f : dec(u);
        }
        float m = fmaxf(fmaxf(v[0], v[1]), fmaxf(v[2], v[3]));
        float s = 0.f;
        #pragma unroll
        for (int c = 0; c < 4; c++) s += expf(v[c] - m);
        float lse = m + logf(s);
        #pragma unroll
        for (int c = 0; c < 4; c++) out[t * 4 + c] = v[c] - lse;
        __syncthreads();
        #pragma unroll
        for (int c = 0; c < 4; c++) g_pool[t * 4 + c] = 0u;
    }
    if (b == 1 && t == 0) g_ovf_cnt = 0;
    int i = b * 256 + t;
    if (i < NN) g_cnt[i] = 0;
}

// ---------------- launch ----------------
extern "C" void kernel_launch(void* const* d_in, const int* in_sizes, int n_in,
                              void* d_out, int out_size) {
    const float* x   = (const float*)d_in[0];
    const void*  ei  = d_in[1];
    const void*  bat = d_in[2];
    const float* W1  = (const float*)d_in[3];
    const float* as1 = (const float*)d_in[4];
    const float* ad1 = (const float*)d_in[5];
    const float* b1  = (const float*)d_in[6];
    const float* W2  = (const float*)d_in[7];
    const float* as2 = (const float*)d_in[8];
    const float* ad2 = (const float*)d_in[9];
    const float* b2  = (const float*)d_in[10];
    const float* W3  = (const float*)d_in[11];
    const float* as3 = (const float*)d_in[12];
    const float* ad3 = (const float*)d_in[13];
    const float* b3  = (const float*)d_in[14];
    float* out = (float*)d_out;

    float *hbuf, *obuf;
    cudaGetSymbolAddress((void**)&hbuf, g_h);
    cudaGetSymbolAddress((void**)&obuf, g_o);

    k_alpha_x<<<(NN + 255) / 256, 256>>>(x, W1, as1, ad1, W2, (const int*)ei);  // 1
    k_fill<<<(NE + 255) / 256, 256>>>(ei);                                      // 2
    k_aggx<<<NN / 8, 256>>>(x);                                                 // 3
    k_gemm2f<<<NN / 64, 256>>>(W1, b1, hbuf, as2, ad2);                         // 4 (profiled)
    k_agg2<<<NN / 8, 256>>>(hbuf, b2, W3, as3, ad3, obuf);                      // 5
    k_agg3<<<NN / 8, 256>>>(obuf, b3, bat);                                     // 6
    k_final<<<(NN + 255) / 256, 256>>>(out);                                    // 7
}

// round 16
// speedup vs baseline: 1.1239x; 1.0639x over previous
#include <cuda_runtime.h>
#include <math.h>

#define NN 80000
#define NE 1280000
#define NGR 256
#define KP 136
#define WPAD 56
#define SLOT 48
#define OVF_MAX 16384

// ---------------- static device scratch (zero at entry, restored at exit) ----------------
__device__ int g_cnt[NN];            // ZERO at entry (restored by k_final)
__device__ int g_ovf_cnt;            // ZERO at entry (restored by k_final)
__device__ int2 g_ovf[OVF_MAX];      // overflow (dst, src) pairs — normally empty
__device__ int g_slot[(size_t)NN * SLOT];
__device__ float g_h[(size_t)NN * 54];
__device__ float g_o[(size_t)NN * 4];
__device__ float g_xagg[(size_t)NN * 27];
__device__ float g_W2p[KP * WPAD];
__device__ __align__(16) float g_W1e[27 * 136];   // zero-expanded block-diagonal W1
__device__ float g_als3[NN];
__device__ float g_ald3[NN];
__device__ float4 g_als[NN];         // layer-1 logits
__device__ float4 g_ald[NN];
__device__ float4 g_als2[NN];        // layer-2 logits (separate buffers: no cross-kernel WAR)
__device__ float4 g_ald2[NN];
__device__ unsigned g_pool[NGR * 4]; // ZERO at entry (0 < enc(-inf))
__device__ int g_nz;

__device__ __forceinline__ unsigned enc(float f) {
    unsigned u = __float_as_uint(f);
    return (u & 0x80000000u) ? ~u : (u | 0x80000000u);
}
__device__ __forceinline__ float dec(unsigned u) {
    return __uint_as_float((u & 0x80000000u) ? (u ^ 0x80000000u) : ~u);
}
__device__ __forceinline__ long long ld_idx(const void* p, long long i, bool is64) {
    if (is64) return ((const long long*)p)[i];
    return (long long)((const int*)p)[i];
}
__device__ __forceinline__ float lrelu_exp(float al) {
    al = (al > 0.f) ? al : 0.2f * al;
    return __expf(fminf(al, 80.f));
}

// ---------------- 1: layer-1 logits + W2 pad + W1e expand + dtype sniff ----------------
__global__ void k_alpha_x(const float* __restrict__ x, const float* __restrict__ W1,
                          const float* __restrict__ a_src, const float* __restrict__ a_dst,
                          const float* __restrict__ W2, const int* ei32) {
    __shared__ float v[2][3][9];
    int t = threadIdx.x;
    int gi = blockIdx.x * blockDim.x + t;
    if (gi < KP * WPAD) {
        int k = gi / WPAD, c = gi - k * WPAD;
        g_W2p[gi] = (k < 135 && c < 54) ? W2[k * 54 + c] : 0.f;
    }
    if (gi < 27 * 136) {
        int j = gi / 136, c = gi - j * 136;
        float val = 0.f;
        if (c < 135 && (c / 45) == (j / 9))
            val = W1[(j % 9) * 135 + c];
        g_W1e[gi] = val;
    }
    if (blockIdx.x == 0 && t < 32) {
        int nz = 0;
        for (int j = t; j < 512; j += 32)
            if (ei32[2 * j + 1] != 0) nz++;
        #pragma unroll
        for (int o = 16; o; o >>= 1) nz += __shfl_xor_sync(0xffffffffu, nz, o);
        if (t == 0) g_nz = nz;   // 0 => int64
    }
    if (t < 54) {
        int side = t / 27, r = t % 27;
        int h = r / 9, k = r % 9;
        const float* a = side ? a_dst : a_src;
        float s = 0.f;
        for (int c = 0; c < 45; c++)
            s += __ldg(&W1[k * 135 + h * 45 + c]) * __ldg(&a[h * 45 + c]);
        v[side][h][k] = s;
    }
    __syncthreads();
    int n = gi;
    if (n >= NN) return;
    float xv[9];
    #pragma unroll
    for (int k = 0; k < 9; k++) xv[k] = x[(size_t)n * 9 + k];
    float s[3], d[3];
    #pragma unroll
    for (int h = 0; h < 3; h++) {
        float ss = 0.f, dd = 0.f;
        #pragma unroll
        for (int k = 0; k < 9; k++) {
            ss += xv[k] * v[0][h][k];
            dd += xv[k] * v[1][h][k];
        }
        s[h] = ss; d[h] = dd;
    }
    g_als[n] = make_float4(s[0], s[1], s[2], 0.f);
    g_ald[n] = make_float4(d[0], d[1], d[2], 0.f);
}

// ---------------- 2: slot-CSR fill (no count, no scan; self-loops implicit) ----------------
__global__ void k_fill(const void* ei) {
    int e = blockIdx.x * blockDim.x + threadIdx.x;
    if (e >= NE) return;
    bool is64 = (g_nz == 0);
    int s = (int)ld_idx(ei, e, is64);
    int d = (int)ld_idx(ei, (long long)NE + e, is64);
    int pos = atomicAdd(&g_cnt[d], 1);
    if (pos < SLOT) {
        g_slot[(size_t)d * SLOT + pos] = s;
    } else {
        int op = atomicAdd(&g_ovf_cnt, 1);
        if (op < OVF_MAX) g_ovf[op] = make_int2(d, s);
    }
}

// ---------------- 3: layer-1 aggregation of raw x, warp/node ----------------
__global__ void k_aggx(const float* __restrict__ x) {
    int wid = (blockIdx.x * blockDim.x + threadIdx.x) >> 5;
    if (wid >= NN) return;
    int lane = threadIdx.x & 31;
    int n = wid;
    int hh = lane / 9, cc = lane - hh * 9;
    bool act = lane < 27;
    int deg = g_cnt[n];
    int inslot = min(deg, SLOT);
    const int* slot = g_slot + (size_t)n * SLOT;
    float4 ald4 = g_ald[n];
    float aldv[3] = { ald4.x, ald4.y, ald4.z };
    float acc = 0.f;
    float ssum[3] = { 0.f, 0.f, 0.f };

    for (int base = 0; base < inslot; base += 32) {
        int cnt = min(32, inslot - base);
        int s_l = 0;
        float e_l[3] = { 0.f, 0.f, 0.f };
        if (lane < cnt) {
            s_l = slot[base + lane];
            float4 a = g_als[s_l];
            e_l[0] = lrelu_exp(a.x + aldv[0]);
            e_l[1] = lrelu_exp(a.y + aldv[1]);
            e_l[2] = lrelu_exp(a.z + aldv[2]);
        }
        #pragma unroll
        for (int h = 0; h < 3; h++) ssum[h] += e_l[h];

        int jj = 0;
        for (; jj + 4 <= cnt; jj += 4) {
            int s0 = __shfl_sync(0xffffffffu, s_l, jj + 0);
            int s1 = __shfl_sync(0xffffffffu, s_l, jj + 1);
            int s2 = __shfl_sync(0xffffffffu, s_l, jj + 2);
            int s3 = __shfl_sync(0xffffffffu, s_l, jj + 3);
            float w0a = __shfl_sync(0xffffffffu, e_l[0], jj + 0);
            float w0b = __shfl_sync(0xffffffffu, e_l[1], jj + 0);
            float w0c = __shfl_sync(0xffffffffu, e_l[2], jj + 0);
            float w1a = __shfl_sync(0xffffffffu, e_l[0], jj + 1);
            float w1b = __shfl_sync(0xffffffffu, e_l[1], jj + 1);
            float w1c = __shfl_sync(0xffffffffu, e_l[2], jj + 1);
            float w2a = __shfl_sync(0xffffffffu, e_l[0], jj + 2);
            float w2b = __shfl_sync(0xffffffffu, e_l[1], jj + 2);
            float w2c = __shfl_sync(0xffffffffu, e_l[2], jj + 2);
            float w3a = __shfl_sync(0xffffffffu, e_l[0], jj + 3);
            float w3b = __shfl_sync(0xffffffffu, e_l[1], jj + 3);
            float w3c = __shfl_sync(0xffffffffu, e_l[2], jj + 3);
            if (act) {
                float x0 = __ldg(&x[(size_t)s0 * 9 + cc]);
                float x1 = __ldg(&x[(size_t)s1 * 9 + cc]);
                float x2 = __ldg(&x[(size_t)s2 * 9 + cc]);
                float x3 = __ldg(&x[(size_t)s3 * 9 + cc]);
                float wa = (hh == 0) ? w0a : (hh == 1) ? w0b : w0c;
                float wb = (hh == 0) ? w1a : (hh == 1) ? w1b : w1c;
                float wc = (hh == 0) ? w2a : (hh == 1) ? w2b : w2c;
                float wd = (hh == 0) ? w3a : (hh == 1) ? w3b : w3c;
                acc += wa * x0;
                acc += wb * x1;
                acc += wc * x2;
                acc += wd * x3;
            }
        }
        for (; jj < cnt; jj++) {
            int s = __shfl_sync(0xffffffffu, s_l, jj);
            float wa0 = __shfl_sync(0xffffffffu, e_l[0], jj);
            float wa1 = __shfl_sync(0xffffffffu, e_l[1], jj);
            float wa2 = __shfl_sync(0xffffffffu, e_l[2], jj);
            if (act) {
                float xv = __ldg(&x[(size_t)s * 9 + cc]);
                float w = (hh == 0) ? wa0 : (hh == 1) ? wa1 : wa2;
                acc += w * xv;
            }
        }
    }
    #pragma unroll
    for (int h = 0; h < 3; h++)
        #pragma unroll
        for (int o = 16; o; o >>= 1)
            ssum[h] += __shfl_xor_sync(0xffffffffu, ssum[h], o);

    // overflow edges (normally none)
    if (deg > SLOT) {
        int on = min(g_ovf_cnt, OVF_MAX);
        for (int i = 0; i < on; i++) {
            int2 p = g_ovf[i];
            if (p.x == n) {
                float4 a = g_als[p.y];
                float e0 = lrelu_exp(a.x + aldv[0]);
                float e1 = lrelu_exp(a.y + aldv[1]);
                float e2 = lrelu_exp(a.z + aldv[2]);
                ssum[0] += e0; ssum[1] += e1; ssum[2] += e2;
                if (act) {
                    float xv = __ldg(&x[(size_t)p.y * 9 + cc]);
                    float w = (hh == 0) ? e0 : (hh == 1) ? e1 : e2;
                    acc += w * xv;
                }
            }
        }
    }
    // implicit self-loop (uniform)
    {
        float4 a = g_als[n];
        float e0 = lrelu_exp(a.x + aldv[0]);
        float e1 = lrelu_exp(a.y + aldv[1]);
        float e2 = lrelu_exp(a.z + aldv[2]);
        ssum[0] += e0; ssum[1] += e1; ssum[2] += e2;
        if (act) {
            float xv = __ldg(&x[(size_t)n * 9 + cc]);
            float w = (hh == 0) ? e0 : (hh == 1) ? e1 : e2;
            acc += w * xv;
        }
    }
    if (act)
        g_xagg[(size_t)n * 27 + lane] = acc / (ssum[hh] + 1e-16f);
}

// ---------------- 4: fused map1 + gemm2 + alpha2 (writes g_als2/g_ald2) ----------------
// 288 threads. phase 2a: 272 quad-tasks (8 rows x 4 channels each), W1e zero-expanded.
__global__ void k_gemm2f(const float* __restrict__ b1,
                         float* __restrict__ Y,
                         const float* __restrict__ a_src, const float* __restrict__ a_dst) {
    constexpr int NPB = 64;
    __shared__ __align__(16) float xs[NPB * KP];
    __shared__ float xa[NPB * 28];
    int tid = threadIdx.x;
    int nodeBase = blockIdx.x * NPB;
    for (int i = tid; i < NPB * 27; i += 288) {
        int r = i / 27, c = i - r * 27;
        xa[r * 28 + c] = g_xagg[(size_t)(nodeBase + r) * 27 + c];
    }
    __syncthreads();

    // ---- phase 2a: o1 tile via quad-tasks (one task per thread, 272 tasks) ----
    if (tid < 272) {
        int g8 = tid / 34;           // row group 0..7
        int q  = tid - g8 * 34;      // channel quad 0..33
        int c0 = q * 4;
        int j0 = (c0 / 45) * 9;
        int j1 = (min(c0 + 3, 134) / 45) * 9 + 9;
        float acc[8][4];
        #pragma unroll
        for (int rr = 0; rr < 8; rr++)
            #pragma unroll
            for (int m = 0; m < 4; m++) acc[rr][m] = 0.f;
        const float* xar = xa + (g8 * 8) * 28;
        for (int j = j0; j < j1; j++) {
            float4 w = __ldg((const float4*)&g_W1e[j * 136 + c0]);
            #pragma unroll
            for (int rr = 0; rr < 8; rr++) {
                float a = xar[rr * 28 + j];
                acc[rr][0] += a * w.x;
                acc[rr][1] += a * w.y;
                acc[rr][2] += a * w.z;
                acc[rr][3] += a * w.w;
            }
        }
        float bb[4];
        #pragma unroll
        for (int m = 0; m < 4; m++) {
            int c = c0 + m;
            bb[m] = (c < 135) ? __ldg(&b1[c]) : 0.f;
        }
        #pragma unroll
        for (int rr = 0; rr < 8; rr++) {
            float4 o;
            o.x = fmaxf(acc[rr][0] + bb[0], 0.f);
            o.y = fmaxf(acc[rr][1] + bb[1], 0.f);
            o.z = fmaxf(acc[rr][2] + bb[2], 0.f);
            o.w = fmaxf(acc[rr][3] + bb[3], 0.f);
            *(float4*)&xs[(g8 * 8 + rr) * KP + c0] = o;
        }
    }
    __syncthreads();

    // ---- phase 2b: GEMM 135->54 + fused layer-2 logits (tid < 256) ----
    if (tid < 256) {
        int ng = tid / 16, j = tid & 15;
        int c0 = j * 4;
        float acc[4][4];
        #pragma unroll
        for (int q = 0; q < 4; q++)
            #pragma unroll
            for (int m = 0; m < 4; m++) acc[q][m] = 0.f;
        const float* xp = xs + (ng * 4) * KP;
        for (int k4 = 0; k4 < KP / 4; k4++) {
            float xr0[4], xr1[4], xr2[4], xr3[4];
            *(float4*)xr0 = *(const float4*)&xp[k4 * 4];
            *(float4*)xr1 = *(const float4*)&xp[KP + k4 * 4];
            *(float4*)xr2 = *(const float4*)&xp[2 * KP + k4 * 4];
            *(float4*)xr3 = *(const float4*)&xp[3 * KP + k4 * 4];
            #pragma unroll
            for (int kk = 0; kk < 4; kk++) {
                float wr[4];
                *(float4*)wr = __ldg((const float4*)&g_W2p[(k4 * 4 + kk) * WPAD + c0]);
                #pragma unroll
                for (int m = 0; m < 4; m++) {
                    acc[0][m] += xr0[kk] * wr[m];
                    acc[1][m] += xr1[kk] * wr[m];
                    acc[2][m] += xr2[kk] * wr[m];
                    acc[3][m] += xr3[kk] * wr[m];
                }
            }
        }
        float as_c[4], ad_c[4];
        #pragma unroll
        for (int m = 0; m < 4; m++) {
            int c = c0 + m;
            as_c[m] = (c < 54) ? __ldg(&a_src[c]) : 0.f;
            ad_c[m] = (c < 54) ? __ldg(&a_dst[c]) : 0.f;
        }
        #pragma unroll
        for (int q = 0; q < 4; q++) {
            int n = nodeBase + ng * 4 + q;
            float ps0 = 0.f, ps1 = 0.f, ps2 = 0.f;
            float pd0 = 0.f, pd1 = 0.f, pd2 = 0.f;
            #pragma unroll
            for (int m = 0; m < 4; m++) {
                int c = c0 + m;
                if (c < 54) {
                    Y[(size_t)n * 54 + c] = acc[q][m];
                    int h = c / 18;
                    float vs = acc[q][m] * as_c[m];
                    float vd = acc[q][m] * ad_c[m];
                    if (h == 0) { ps0 += vs; pd0 += vd; }
                    else if (h == 1) { ps1 += vs; pd1 += vd; }
                    else { ps2 += vs; pd2 += vd; }
                }
            }
            #pragma unroll
            for (int o = 8; o; o >>= 1) {
                ps0 += __shfl_xor_sync(0xffffffffu, ps0, o);
                ps1 += __shfl_xor_sync(0xffffffffu, ps1, o);
                ps2 += __shfl_xor_sync(0xffffffffu, ps2, o);
                pd0 += __shfl_xor_sync(0xffffffffu, pd0, o);
                pd1 += __shfl_xor_sync(0xffffffffu, pd1, o);
                pd2 += __shfl_xor_sync(0xffffffffu, pd2, o);
            }
            if (j == 0) {
                g_als2[n] = make_float4(ps0, ps1, ps2, 0.f);
                g_ald2[n] = make_float4(pd0, pd1, pd2, 0.f);
            }
        }
    }
}

// ---------------- 5: agg2 + fused gemm3 + layer-3 logits ----------------
__global__ void k_agg2(const float* __restrict__ hfeat,
                       const float* __restrict__ bias,
                       const float* __restrict__ W3,
                       const float* __restrict__ as3, const float* __restrict__ ad3,
                       float* __restrict__ h3out) {
    int wid = (blockIdx.x * blockDim.x + threadIdx.x) >> 5;
    if (wid >= NN) return;
    int lane = threadIdx.x & 31;
    int n = wid;
    bool act = lane < 27;
    int c0 = 2 * lane;
    int hd = lane / 9;
    int deg = g_cnt[n];
    int inslot = min(deg, SLOT);
    const int* slot = g_slot + (size_t)n * SLOT;
    float4 ald4 = g_ald2[n];
    float aldv[3] = { ald4.x, ald4.y, ald4.z };
    float2 acc = make_float2(0.f, 0.f);
    float ssum0 = 0.f, ssum1 = 0.f, ssum2 = 0.f;

    for (int base = 0; base < inslot; base += 32) {
        int cnt = min(32, inslot - base);
        int s_l = 0;
        float e_l[3] = { 0.f, 0.f, 0.f };
        if (lane < cnt) {
            s_l = slot[base + lane];
            float4 a = g_als2[s_l];
            e_l[0] = lrelu_exp(a.x + aldv[0]);
            e_l[1] = lrelu_exp(a.y + aldv[1]);
            e_l[2] = lrelu_exp(a.z + aldv[2]);
        }
        ssum0 += e_l[0]; ssum1 += e_l[1]; ssum2 += e_l[2];

        int jj = 0;
        for (; jj + 4 <= cnt; jj += 4) {
            int s0 = __shfl_sync(0xffffffffu, s_l, jj + 0);
            int s1 = __shfl_sync(0xffffffffu, s_l, jj + 1);
            int s2 = __shfl_sync(0xffffffffu, s_l, jj + 2);
            int s3 = __shfl_sync(0xffffffffu, s_l, jj + 3);
            float w0a = __shfl_sync(0xffffffffu, e_l[0], jj + 0);
            float w0b = __shfl_sync(0xffffffffu, e_l[1], jj + 0);
            float w0c = __shfl_sync(0xffffffffu, e_l[2], jj + 0);
            float w1a = __shfl_sync(0xffffffffu, e_l[0], jj + 1);
            float w1b = __shfl_sync(0xffffffffu, e_l[1], jj + 1);
            float w1c = __shfl_sync(0xffffffffu, e_l[2], jj + 1);
            float w2a = __shfl_sync(0xffffffffu, e_l[0], jj + 2);
            float w2b = __shfl_sync(0xffffffffu, e_l[1], jj + 2);
            float w2c = __shfl_sync(0xffffffffu, e_l[2], jj + 2);
            float w3a = __shfl_sync(0xffffffffu, e_l[0], jj + 3);
            float w3b = __shfl_sync(0xffffffffu, e_l[1], jj + 3);
            float w3c = __shfl_sync(0xffffffffu, e_l[2], jj + 3);
            if (act) {
                float2 g0 = *(const float2*)&hfeat[(size_t)s0 * 54 + c0];
                float2 g1 = *(const float2*)&hfeat[(size_t)s1 * 54 + c0];
                float2 g2 = *(const float2*)&hfeat[(size_t)s2 * 54 + c0];
                float2 g3 = *(const float2*)&hfeat[(size_t)s3 * 54 + c0];
                float wa = (hd == 0) ? w0a : (hd == 1) ? w0b : w0c;
                float wb = (hd == 0) ? w1a : (hd == 1) ? w1b : w1c;
                float wc = (hd == 0) ? w2a : (hd == 1) ? w2b : w2c;
                float wd = (hd == 0) ? w3a : (hd == 1) ? w3b : w3c;
                acc.x += wa * g0.x; acc.y += wa * g0.y;
                acc.x += wb * g1.x; acc.y += wb * g1.y;
                acc.x += wc * g2.x; acc.y += wc * g2.y;
                acc.x += wd * g3.x; acc.y += wd * g3.y;
            }
        }
        for (; jj < cnt; jj++) {
            int s = __shfl_sync(0xffffffffu, s_l, jj);
            float wa0 = __shfl_sync(0xffffffffu, e_l[0], jj);
            float wa1 = __shfl_sync(0xffffffffu, e_l[1], jj);
            float wa2 = __shfl_sync(0xffffffffu, e_l[2], jj);
            if (act) {
                float2 g = *(const float2*)&hfeat[(size_t)s * 54 + c0];
                float ww = (hd == 0) ? wa0 : (hd == 1) ? wa1 : wa2;
                acc.x += ww * g.x; acc.y += ww * g.y;
            }
        }
    }
    #pragma unroll
    for (int o = 16; o; o >>= 1) {
        ssum0 += __shfl_xor_sync(0xffffffffu, ssum0, o);
        ssum1 += __shfl_xor_sync(0xffffffffu, ssum1, o);
        ssum2 += __shfl_xor_sync(0xffffffffu, ssum2, o);
    }
    // overflow edges (normally none)
    if (deg > SLOT) {
        int on = min(g_ovf_cnt, OVF_MAX);
        for (int i = 0; i < on; i++) {
            int2 p = g_ovf[i];
            if (p.x == n) {
                float4 a = g_als2[p.y];
                float e0 = lrelu_exp(a.x + aldv[0]);
                float e1 = lrelu_exp(a.y + aldv[1]);
                float e2 = lrelu_exp(a.z + aldv[2]);
                ssum0 += e0; ssum1 += e1; ssum2 += e2;
                if (act) {
                    float2 g = *(const float2*)&hfeat[(size_t)p.y * 54 + c0];
                    float ww = (hd == 0) ? e0 : (hd == 1) ? e1 : e2;
                    acc.x += ww * g.x; acc.y += ww * g.y;
                }
            }
        }
    }
    // implicit self-loop (uniform)
    {
        float4 a = g_als2[n];
        float e0 = lrelu_exp(a.x + aldv[0]);
        float e1 = lrelu_exp(a.y + aldv[1]);
        float e2 = lrelu_exp(a.z + aldv[2]);
        ssum0 += e0; ssum1 += e1; ssum2 += e2;
        if (act) {
            float2 g = *(const float2*)&hfeat[(size_t)n * 54 + c0];
            float ww = (hd == 0) ? e0 : (hd == 1) ? e1 : e2;
            acc.x += ww * g.x; acc.y += ww * g.y;
        }
    }
    float2 o2 = make_float2(0.f, 0.f);
    if (act) {
        float ss = (hd == 0) ? ssum0 : (hd == 1) ? ssum1 : ssum2;
        float inv = 1.f / (ss + 1e-16f);
        o2.x = fmaxf(acc.x * inv + __ldg(&bias[c0]), 0.f);
        o2.y = fmaxf(acc.y * inv + __ldg(&bias[c0 + 1]), 0.f);
    }
    float t0 = 0.f, t1 = 0.f, t2 = 0.f, t3 = 0.f;
    if (act) {
        float4 wr0 = __ldg((const float4*)&W3[c0 * 4]);
        float4 wr1 = __ldg((const float4*)&W3[(c0 + 1) * 4]);
        t0 = o2.x * wr0.x + o2.y * wr1.x;
        t1 = o2.x * wr0.y + o2.y * wr1.y;
        t2 = o2.x * wr0.z + o2.y * wr1.z;
        t3 = o2.x * wr0.w + o2.y * wr1.w;
    }
    #pragma unroll
    for (int o = 16; o; o >>= 1) {
        t0 += __shfl_xor_sync(0xffffffffu, t0, o);
        t1 += __shfl_xor_sync(0xffffffffu, t1, o);
        t2 += __shfl_xor_sync(0xffffffffu, t2, o);
        t3 += __shfl_xor_sync(0xffffffffu, t3, o);
    }
    if (lane == 0) {
        *(float4*)&h3out[(size_t)n * 4] = make_float4(t0, t1, t2, t3);
        g_als3[n] = t0 * __ldg(&as3[0]) + t1 * __ldg(&as3[1]) + t2 * __ldg(&as3[2]) + t3 * __ldg(&as3[3]);
        g_ald3[n] = t0 * __ldg(&ad3[0]) + t1 * __ldg(&ad3[1]) + t2 * __ldg(&ad3[2]) + t3 * __ldg(&ad3[3]);
    }
}

// ---------------- 6: layer-3 agg + global max pool ----------------
__global__ void k_agg3(const float* __restrict__ hfeat,
                       const float* __restrict__ bias,
                       const void* __restrict__ batch) {
    int wid = (blockIdx.x * blockDim.x + threadIdx.x) >> 5;
    if (wid >= NN) return;
    int lane = threadIdx.x & 31;
    int sub = lane >> 2, c = lane & 3;
    int n = wid;
    int deg = g_cnt[n];
    int inslot = min(deg, SLOT);
    const int* slot = g_slot + (size_t)n * SLOT;
    float aldn = g_ald3[n];
    float acc = 0.f, wsum = 0.f;
    for (int e0 = 0; e0 < inslot; e0 += 8) {
        int e = e0 + sub;
        if (e < inslot) {
            int s = slot[e];
            float w = lrelu_exp(g_als3[s] + aldn);
            acc += w * __ldg(&hfeat[(size_t)s * 4 + c]);
            wsum += w;
        }
    }
    #pragma unroll
    for (int o = 4; o < 32; o <<= 1) {
        acc += __shfl_xor_sync(0xffffffffu, acc, o);
        wsum += __shfl_xor_sync(0xffffffffu, wsum, o);
    }
    // overflow edges (normally none)
    if (deg > SLOT) {
        int on = min(g_ovf_cnt, OVF_MAX);
        for (int i = 0; i < on; i++) {
            int2 p = g_ovf[i];
            if (p.x == n) {
                float w = lrelu_exp(g_als3[p.y] + aldn);
                acc += w * __ldg(&hfeat[(size_t)p.y * 4 + c]);
                wsum += w;
            }
        }
    }
    // implicit self-loop (uniform per channel)
    {
        float w = lrelu_exp(g_als3[n] + aldn);
        acc += w * __ldg(&hfeat[(size_t)n * 4 + c]);
        wsum += w;
    }
    if (lane < 4) {
        float o = acc / (wsum + 1e-16f) + __ldg(&bias[lane]);
        bool is64 = (g_nz == 0);
        int g = (int)ld_idx(batch, n, is64);
        atomicMax(&g_pool[g * 4 + lane], enc(o));
    }
}

// ---------------- 7: log-softmax + restore clean state ----------------
__global__ void k_final(float* __restrict__ out) {
    int b = blockIdx.x, t = threadIdx.x;
    if (b == 0) {
        float v[4];
        #pragma unroll
        for (int c = 0; c < 4; c++) {
            unsigned u = g_pool[t * 4 + c];
            v[c] = (u <= 0x007FFFFFu) ? -1e9f : dec(u);
        }
        float m = fmaxf(fmaxf(v[0], v[1]), fmaxf(v[2], v[3]));
        float s = 0.f;
        #pragma unroll
        for (int c = 0; c < 4; c++) s += expf(v[c] - m);
        float lse = m + logf(s);
        #pragma unroll
        for (int c = 0; c < 4; c++) out[t * 4 + c] = v[c] - lse;
        __syncthreads();
        #pragma unroll
        for (int c = 0; c < 4; c++) g_pool[t * 4 + c] = 0u;
    }
    if (b == 1 && t == 0) g_ovf_cnt = 0;
    int i = b * 256 + t;
    if (i < NN) g_cnt[i] = 0;
}

// ---------------- launch ----------------
extern "C" void kernel_launch(void* const* d_in, const int* in_sizes, int n_in,
                              void* d_out, int out_size) {
    const float* x   = (const float*)d_in[0];
    const void*  ei  = d_in[1];
    const void*  bat = d_in[2];
    const float* W1  = (const float*)d_in[3];
    const float* as1 = (const float*)d_in[4];
    const float* ad1 = (const float*)d_in[5];
    const float* b1  = (const float*)d_in[6];
    const float* W2  = (const float*)d_in[7];
    const float* as2 = (const float*)d_in[8];
    const float* ad2 = (const float*)d_in[9];
    const float* b2  = (const float*)d_in[10];
    const float* W3  = (const float*)d_in[11];
    const float* as3 = (const float*)d_in[12];
    const float* ad3 = (const float*)d_in[13];
    const float* b3  = (const float*)d_in[14];
    float* out = (float*)d_out;

    float *hbuf, *obuf;
    cudaGetSymbolAddress((void**)&hbuf, g_h);
    cudaGetSymbolAddress((void**)&obuf, g_o);

    k_alpha_x<<<(NN + 255) / 256, 256>>>(x, W1, as1, ad1, W2, (const int*)ei);  // 1
    k_fill<<<(NE + 255) / 256, 256>>>(ei);                                      // 2
    k_aggx<<<NN / 8, 256>>>(x);                                                 // 3
    k_gemm2f<<<NN / 64, 288>>>(b1, hbuf, as2, ad2);                             // 4 (profiled)
    k_agg2<<<NN / 8, 256>>>(hbuf, b2, W3, as3, ad3, obuf);                      // 5
    k_agg3<<<NN / 8, 256>>>(obuf, b3, bat);                                     // 6
    k_final<<<(NN + 255) / 256, 256>>>(out);                                    // 7
}

// round 17
// speedup vs baseline: 1.1368x; 1.0115x over previous
#include <cuda_runtime.h>
#include <math.h>

#define NN 80000
#define NE 1280000
#define NGR 256
#define KP 136
#define WPAD 56
#define SLOT 48
#define OVF_MAX 16384

// ---------------- static device scratch (zero at entry, restored at exit) ----------------
__device__ int g_cnt[NN];            // ZERO at entry (restored by k_final)
__device__ int g_ovf_cnt;            // ZERO at entry (restored by k_final)
__device__ int2 g_ovf[OVF_MAX];      // overflow (dst, src) pairs — normally empty
__device__ int g_slot[(size_t)NN * SLOT];
__device__ __align__(16) float g_pk1[(size_t)NN * 16];  // {als1.xyz, 0, x[9], pad} 64B/node
__device__ __align__(16) float g_pk2[(size_t)NN * 64];  // {als2 float4, h[54], pad} 256B/node
__device__ float g_o[(size_t)NN * 4];
__device__ float g_xagg[(size_t)NN * 27];
__device__ float g_W2p[KP * WPAD];
__device__ __align__(16) float g_W1e[27 * 136];   // zero-expanded block-diagonal W1
__device__ float g_als3[NN];
__device__ float g_ald3[NN];
__device__ float4 g_ald[NN];         // layer-1 dst logits
__device__ float4 g_ald2[NN];        // layer-2 dst logits
__device__ unsigned g_pool[NGR * 4]; // ZERO at entry (0 < enc(-inf))
__device__ int g_nz;

__device__ __forceinline__ unsigned enc(float f) {
    unsigned u = __float_as_uint(f);
    return (u & 0x80000000u) ? ~u : (u | 0x80000000u);
}
__device__ __forceinline__ float dec(unsigned u) {
    return __uint_as_float((u & 0x80000000u) ? (u ^ 0x80000000u) : ~u);
}
__device__ __forceinline__ long long ld_idx(const void* p, long long i, bool is64) {
    if (is64) return ((const long long*)p)[i];
    return (long long)((const int*)p)[i];
}
__device__ __forceinline__ float lrelu_exp(float al) {
    al = (al > 0.f) ? al : 0.2f * al;
    return __expf(fminf(al, 80.f));
}

// ---------------- 1: layer-1 logits (packed with x) + W2 pad + W1e expand + sniff ----------------
__global__ void k_alpha_x(const float* __restrict__ x, const float* __restrict__ W1,
                          const float* __restrict__ a_src, const float* __restrict__ a_dst,
                          const float* __restrict__ W2, const int* ei32) {
    __shared__ float v[2][3][9];
    int t = threadIdx.x;
    int gi = blockIdx.x * blockDim.x + t;
    if (gi < KP * WPAD) {
        int k = gi / WPAD, c = gi - k * WPAD;
        g_W2p[gi] = (k < 135 && c < 54) ? W2[k * 54 + c] : 0.f;
    }
    if (gi < 27 * 136) {
        int j = gi / 136, c = gi - j * 136;
        float val = 0.f;
        if (c < 135 && (c / 45) == (j / 9))
            val = W1[(j % 9) * 135 + c];
        g_W1e[gi] = val;
    }
    if (blockIdx.x == 0 && t < 32) {
        int nz = 0;
        for (int j = t; j < 512; j += 32)
            if (ei32[2 * j + 1] != 0) nz++;
        #pragma unroll
        for (int o = 16; o; o >>= 1) nz += __shfl_xor_sync(0xffffffffu, nz, o);
        if (t == 0) g_nz = nz;   // 0 => int64
    }
    if (t < 54) {
        int side = t / 27, r = t % 27;
        int h = r / 9, k = r % 9;
        const float* a = side ? a_dst : a_src;
        float s = 0.f;
        for (int c = 0; c < 45; c++)
            s += __ldg(&W1[k * 135 + h * 45 + c]) * __ldg(&a[h * 45 + c]);
        v[side][h][k] = s;
    }
    __syncthreads();
    int n = gi;
    if (n >= NN) return;
    float xv[9];
    #pragma unroll
    for (int k = 0; k < 9; k++) xv[k] = x[(size_t)n * 9 + k];
    float s[3], d[3];
    #pragma unroll
    for (int h = 0; h < 3; h++) {
        float ss = 0.f, dd = 0.f;
        #pragma unroll
        for (int k = 0; k < 9; k++) {
            ss += xv[k] * v[0][h][k];
            dd += xv[k] * v[1][h][k];
        }
        s[h] = ss; d[h] = dd;
    }
    float* pk = &g_pk1[(size_t)n * 16];
    *(float4*)pk = make_float4(s[0], s[1], s[2], 0.f);
    #pragma unroll
    for (int k = 0; k < 9; k++) pk[4 + k] = xv[k];
    g_ald[n] = make_float4(d[0], d[1], d[2], 0.f);
}

// ---------------- 2: slot-CSR fill ----------------
__global__ void k_fill(const void* ei) {
    int e = blockIdx.x * blockDim.x + threadIdx.x;
    if (e >= NE) return;
    bool is64 = (g_nz == 0);
    int s = (int)ld_idx(ei, e, is64);
    int d = (int)ld_idx(ei, (long long)NE + e, is64);
    int pos = atomicAdd(&g_cnt[d], 1);
    if (pos < SLOT) {
        g_slot[(size_t)d * SLOT + pos] = s;
    } else {
        int op = atomicAdd(&g_ovf_cnt, 1);
        if (op < OVF_MAX) g_ovf[op] = make_int2(d, s);
    }
}

// ---------------- 3: layer-1 aggregation (packed reads: 1 line/edge) ----------------
__global__ void k_aggx() {
    int wid = (blockIdx.x * blockDim.x + threadIdx.x) >> 5;
    if (wid >= NN) return;
    int lane = threadIdx.x & 31;
    int n = wid;
    int hh = lane / 9, cc = lane - hh * 9;
    bool act = lane < 27;
    int deg = g_cnt[n];
    int inslot = min(deg, SLOT);
    const int* slot = g_slot + (size_t)n * SLOT;
    float4 ald4 = g_ald[n];
    float aldv[3] = { ald4.x, ald4.y, ald4.z };
    float acc = 0.f;
    float ssum[3] = { 0.f, 0.f, 0.f };

    for (int base = 0; base < inslot; base += 32) {
        int cnt = min(32, inslot - base);
        int s_l = 0;
        float e_l[3] = { 0.f, 0.f, 0.f };
        if (lane < cnt) {
            s_l = slot[base + lane];
            float4 a = *(const float4*)&g_pk1[(size_t)s_l * 16];
            e_l[0] = lrelu_exp(a.x + aldv[0]);
            e_l[1] = lrelu_exp(a.y + aldv[1]);
            e_l[2] = lrelu_exp(a.z + aldv[2]);
        }
        #pragma unroll
        for (int h = 0; h < 3; h++) ssum[h] += e_l[h];

        int jj = 0;
        for (; jj + 4 <= cnt; jj += 4) {
            int s0 = __shfl_sync(0xffffffffu, s_l, jj + 0);
            int s1 = __shfl_sync(0xffffffffu, s_l, jj + 1);
            int s2 = __shfl_sync(0xffffffffu, s_l, jj + 2);
            int s3 = __shfl_sync(0xffffffffu, s_l, jj + 3);
            float w0a = __shfl_sync(0xffffffffu, e_l[0], jj + 0);
            float w0b = __shfl_sync(0xffffffffu, e_l[1], jj + 0);
            float w0c = __shfl_sync(0xffffffffu, e_l[2], jj + 0);
            float w1a = __shfl_sync(0xffffffffu, e_l[0], jj + 1);
            float w1b = __shfl_sync(0xffffffffu, e_l[1], jj + 1);
            float w1c = __shfl_sync(0xffffffffu, e_l[2], jj + 1);
            float w2a = __shfl_sync(0xffffffffu, e_l[0], jj + 2);
            float w2b = __shfl_sync(0xffffffffu, e_l[1], jj + 2);
            float w2c = __shfl_sync(0xffffffffu, e_l[2], jj + 2);
            float w3a = __shfl_sync(0xffffffffu, e_l[0], jj + 3);
            float w3b = __shfl_sync(0xffffffffu, e_l[1], jj + 3);
            float w3c = __shfl_sync(0xffffffffu, e_l[2], jj + 3);
            if (act) {
                float x0 = __ldg(&g_pk1[(size_t)s0 * 16 + 4 + cc]);
                float x1 = __ldg(&g_pk1[(size_t)s1 * 16 + 4 + cc]);
                float x2 = __ldg(&g_pk1[(size_t)s2 * 16 + 4 + cc]);
                float x3 = __ldg(&g_pk1[(size_t)s3 * 16 + 4 + cc]);
                float wa = (hh == 0) ? w0a : (hh == 1) ? w0b : w0c;
                float wb = (hh == 0) ? w1a : (hh == 1) ? w1b : w1c;
                float wc = (hh == 0) ? w2a : (hh == 1) ? w2b : w2c;
                float wd = (hh == 0) ? w3a : (hh == 1) ? w3b : w3c;
                acc += wa * x0;
                acc += wb * x1;
                acc += wc * x2;
                acc += wd * x3;
            }
        }
        for (; jj < cnt; jj++) {
            int s = __shfl_sync(0xffffffffu, s_l, jj);
            float wa0 = __shfl_sync(0xffffffffu, e_l[0], jj);
            float wa1 = __shfl_sync(0xffffffffu, e_l[1], jj);
            float wa2 = __shfl_sync(0xffffffffu, e_l[2], jj);
            if (act) {
                float xv = __ldg(&g_pk1[(size_t)s * 16 + 4 + cc]);
                float w = (hh == 0) ? wa0 : (hh == 1) ? wa1 : wa2;
                acc += w * xv;
            }
        }
    }
    #pragma unroll
    for (int h = 0; h < 3; h++)
        #pragma unroll
        for (int o = 16; o; o >>= 1)
            ssum[h] += __shfl_xor_sync(0xffffffffu, ssum[h], o);

    // overflow edges (normally none)
    if (deg > SLOT) {
        int on = min(g_ovf_cnt, OVF_MAX);
        for (int i = 0; i < on; i++) {
            int2 p = g_ovf[i];
            if (p.x == n) {
                float4 a = *(const float4*)&g_pk1[(size_t)p.y * 16];
                float e0 = lrelu_exp(a.x + aldv[0]);
                float e1 = lrelu_exp(a.y + aldv[1]);
                float e2 = lrelu_exp(a.z + aldv[2]);
                ssum[0] += e0; ssum[1] += e1; ssum[2] += e2;
                if (act) {
                    float xv = __ldg(&g_pk1[(size_t)p.y * 16 + 4 + cc]);
                    float w = (hh == 0) ? e0 : (hh == 1) ? e1 : e2;
                    acc += w * xv;
                }
            }
        }
    }
    // implicit self-loop (uniform)
    {
        float4 a = *(const float4*)&g_pk1[(size_t)n * 16];
        float e0 = lrelu_exp(a.x + aldv[0]);
        float e1 = lrelu_exp(a.y + aldv[1]);
        float e2 = lrelu_exp(a.z + aldv[2]);
        ssum[0] += e0; ssum[1] += e1; ssum[2] += e2;
        if (act) {
            float xv = __ldg(&g_pk1[(size_t)n * 16 + 4 + cc]);
            float w = (hh == 0) ? e0 : (hh == 1) ? e1 : e2;
            acc += w * xv;
        }
    }
    if (act)
        g_xagg[(size_t)n * 27 + lane] = acc / (ssum[hh] + 1e-16f);
}

// ---------------- 4: fused map1 + gemm2 + alpha2 (writes packed g_pk2) ----------------
__global__ void k_gemm2f(const float* __restrict__ b1,
                         const float* __restrict__ a_src, const float* __restrict__ a_dst) {
    constexpr int NPB = 64;
    __shared__ __align__(16) float xs[NPB * KP];
    __shared__ float xa[NPB * 28];
    int tid = threadIdx.x;
    int nodeBase = blockIdx.x * NPB;
    for (int i = tid; i < NPB * 27; i += 288) {
        int r = i / 27, c = i - r * 27;
        xa[r * 28 + c] = g_xagg[(size_t)(nodeBase + r) * 27 + c];
    }
    __syncthreads();

    // ---- phase 2a: o1 tile via quad-tasks (one task per thread, 272 tasks) ----
    if (tid < 272) {
        int g8 = tid / 34;
        int q  = tid - g8 * 34;
        int c0 = q * 4;
        int j0 = (c0 / 45) * 9;
        int j1 = (min(c0 + 3, 134) / 45) * 9 + 9;
        float acc[8][4];
        #pragma unroll
        for (int rr = 0; rr < 8; rr++)
            #pragma unroll
            for (int m = 0; m < 4; m++) acc[rr][m] = 0.f;
        const float* xar = xa + (g8 * 8) * 28;
        for (int j = j0; j < j1; j++) {
            float4 w = __ldg((const float4*)&g_W1e[j * 136 + c0]);
            #pragma unroll
            for (int rr = 0; rr < 8; rr++) {
                float a = xar[rr * 28 + j];
                acc[rr][0] += a * w.x;
                acc[rr][1] += a * w.y;
                acc[rr][2] += a * w.z;
                acc[rr][3] += a * w.w;
            }
        }
        float bb[4];
        #pragma unroll
        for (int m = 0; m < 4; m++) {
            int c = c0 + m;
            bb[m] = (c < 135) ? __ldg(&b1[c]) : 0.f;
        }
        #pragma unroll
        for (int rr = 0; rr < 8; rr++) {
            float4 o;
            o.x = fmaxf(acc[rr][0] + bb[0], 0.f);
            o.y = fmaxf(acc[rr][1] + bb[1], 0.f);
            o.z = fmaxf(acc[rr][2] + bb[2], 0.f);
            o.w = fmaxf(acc[rr][3] + bb[3], 0.f);
            *(float4*)&xs[(g8 * 8 + rr) * KP + c0] = o;
        }
    }
    __syncthreads();

    // ---- phase 2b: GEMM 135->54 + fused layer-2 logits ----
    if (tid < 256) {
        int ng = tid / 16, j = tid & 15;
        int c0 = j * 4;
        float acc[4][4];
        #pragma unroll
        for (int q = 0; q < 4; q++)
            #pragma unroll
            for (int m = 0; m < 4; m++) acc[q][m] = 0.f;
        const float* xp = xs + (ng * 4) * KP;
        for (int k4 = 0; k4 < KP / 4; k4++) {
            float xr0[4], xr1[4], xr2[4], xr3[4];
            *(float4*)xr0 = *(const float4*)&xp[k4 * 4];
            *(float4*)xr1 = *(const float4*)&xp[KP + k4 * 4];
            *(float4*)xr2 = *(const float4*)&xp[2 * KP + k4 * 4];
            *(float4*)xr3 = *(const float4*)&xp[3 * KP + k4 * 4];
            #pragma unroll
            for (int kk = 0; kk < 4; kk++) {
                float wr[4];
                *(float4*)wr = __ldg((const float4*)&g_W2p[(k4 * 4 + kk) * WPAD + c0]);
                #pragma unroll
                for (int m = 0; m < 4; m++) {
                    acc[0][m] += xr0[kk] * wr[m];
                    acc[1][m] += xr1[kk] * wr[m];
                    acc[2][m] += xr2[kk] * wr[m];
                    acc[3][m] += xr3[kk] * wr[m];
                }
            }
        }
        float as_c[4], ad_c[4];
        #pragma unroll
        for (int m = 0; m < 4; m++) {
            int c = c0 + m;
            as_c[m] = (c < 54) ? __ldg(&a_src[c]) : 0.f;
            ad_c[m] = (c < 54) ? __ldg(&a_dst[c]) : 0.f;
        }
        #pragma unroll
        for (int q = 0; q < 4; q++) {
            int n = nodeBase + ng * 4 + q;
            float ps0 = 0.f, ps1 = 0.f, ps2 = 0.f;
            float pd0 = 0.f, pd1 = 0.f, pd2 = 0.f;
            #pragma unroll
            for (int m = 0; m < 4; m++) {
                int c = c0 + m;
                if (c < 54) {
                    g_pk2[(size_t)n * 64 + 4 + c] = acc[q][m];
                    int h = c / 18;
                    float vs = acc[q][m] * as_c[m];
                    float vd = acc[q][m] * ad_c[m];
                    if (h == 0) { ps0 += vs; pd0 += vd; }
                    else if (h == 1) { ps1 += vs; pd1 += vd; }
                    else { ps2 += vs; pd2 += vd; }
                }
            }
            #pragma unroll
            for (int o = 8; o; o >>= 1) {
                ps0 += __shfl_xor_sync(0xffffffffu, ps0, o);
                ps1 += __shfl_xor_sync(0xffffffffu, ps1, o);
                ps2 += __shfl_xor_sync(0xffffffffu, ps2, o);
                pd0 += __shfl_xor_sync(0xffffffffu, pd0, o);
                pd1 += __shfl_xor_sync(0xffffffffu, pd1, o);
                pd2 += __shfl_xor_sync(0xffffffffu, pd2, o);
            }
            if (j == 0) {
                *(float4*)&g_pk2[(size_t)n * 64] = make_float4(ps0, ps1, ps2, 0.f);
                g_ald2[n] = make_float4(pd0, pd1, pd2, 0.f);
            }
        }
    }
}

// ---------------- 5: agg2 + fused gemm3 + layer-3 logits (packed reads: 2 lines/edge) ----------------
__global__ void k_agg2(const float* __restrict__ bias,
                       const float* __restrict__ W3,
                       const float* __restrict__ as3, const float* __restrict__ ad3,
                       float* __restrict__ h3out) {
    int wid = (blockIdx.x * blockDim.x + threadIdx.x) >> 5;
    if (wid >= NN) return;
    int lane = threadIdx.x & 31;
    int n = wid;
    bool act = lane < 27;
    int c0 = 2 * lane;
    int hd = lane / 9;
    int deg = g_cnt[n];
    int inslot = min(deg, SLOT);
    const int* slot = g_slot + (size_t)n * SLOT;
    float4 ald4 = g_ald2[n];
    float aldv[3] = { ald4.x, ald4.y, ald4.z };
    float2 acc = make_float2(0.f, 0.f);
    float ssum0 = 0.f, ssum1 = 0.f, ssum2 = 0.f;

    for (int base = 0; base < inslot; base += 32) {
        int cnt = min(32, inslot - base);
        int s_l = 0;
        float e_l[3] = { 0.f, 0.f, 0.f };
        if (lane < cnt) {
            s_l = slot[base + lane];
            float4 a = *(const float4*)&g_pk2[(size_t)s_l * 64];
            e_l[0] = lrelu_exp(a.x + aldv[0]);
            e_l[1] = lrelu_exp(a.y + aldv[1]);
            e_l[2] = lrelu_exp(a.z + aldv[2]);
        }
        ssum0 += e_l[0]; ssum1 += e_l[1]; ssum2 += e_l[2];

        int jj = 0;
        for (; jj + 4 <= cnt; jj += 4) {
            int s0 = __shfl_sync(0xffffffffu, s_l, jj + 0);
            int s1 = __shfl_sync(0xffffffffu, s_l, jj + 1);
            int s2 = __shfl_sync(0xffffffffu, s_l, jj + 2);
            int s3 = __shfl_sync(0xffffffffu, s_l, jj + 3);
            float w0a = __shfl_sync(0xffffffffu, e_l[0], jj + 0);
            float w0b = __shfl_sync(0xffffffffu, e_l[1], jj + 0);
            float w0c = __shfl_sync(0xffffffffu, e_l[2], jj + 0);
            float w1a = __shfl_sync(0xffffffffu, e_l[0], jj + 1);
            float w1b = __shfl_sync(0xffffffffu, e_l[1], jj + 1);
            float w1c = __shfl_sync(0xffffffffu, e_l[2], jj + 1);
            float w2a = __shfl_sync(0xffffffffu, e_l[0], jj + 2);
            float w2b = __shfl_sync(0xffffffffu, e_l[1], jj + 2);
            float w2c = __shfl_sync(0xffffffffu, e_l[2], jj + 2);
            float w3a = __shfl_sync(0xffffffffu, e_l[0], jj + 3);
            float w3b = __shfl_sync(0xffffffffu, e_l[1], jj + 3);
            float w3c = __shfl_sync(0xffffffffu, e_l[2], jj + 3);
            if (act) {
                float2 g0 = *(const float2*)&g_pk2[(size_t)s0 * 64 + 4 + c0];
                float2 g1 = *(const float2*)&g_pk2[(size_t)s1 * 64 + 4 + c0];
                float2 g2 = *(const float2*)&g_pk2[(size_t)s2 * 64 + 4 + c0];
                float2 g3 = *(const float2*)&g_pk2[(size_t)s3 * 64 + 4 + c0];
                float wa = (hd == 0) ? w0a : (hd == 1) ? w0b : w0c;
                float wb = (hd == 0) ? w1a : (hd == 1) ? w1b : w1c;
                float wc = (hd == 0) ? w2a : (hd == 1) ? w2b : w2c;
                float wd = (hd == 0) ? w3a : (hd == 1) ? w3b : w3c;
                acc.x += wa * g0.x; acc.y += wa * g0.y;
                acc.x += wb * g1.x; acc.y += wb * g1.y;
                acc.x += wc * g2.x; acc.y += wc * g2.y;
                acc.x += wd * g3.x; acc.y += wd * g3.y;
            }
        }
        for (; jj < cnt; jj++) {
            int s = __shfl_sync(0xffffffffu, s_l, jj);
            float wa0 = __shfl_sync(0xffffffffu, e_l[0], jj);
            float wa1 = __shfl_sync(0xffffffffu, e_l[1], jj);
            float wa2 = __shfl_sync(0xffffffffu, e_l[2], jj);
            if (act) {
                float2 g = *(const float2*)&g_pk2[(size_t)s * 64 + 4 + c0];
                float ww = (hd == 0) ? wa0 : (hd == 1) ? wa1 : wa2;
                acc.x += ww * g.x; acc.y += ww * g.y;
            }
        }
    }
    #pragma unroll
    for (int o = 16; o; o >>= 1) {
        ssum0 += __shfl_xor_sync(0xffffffffu, ssum0, o);
        ssum1 += __shfl_xor_sync(0xffffffffu, ssum1, o);
        ssum2 += __shfl_xor_sync(0xffffffffu, ssum2, o);
    }
    // overflow edges (normally none)
    if (deg > SLOT) {
        int on = min(g_ovf_cnt, OVF_MAX);
        for (int i = 0; i < on; i++) {
            int2 p = g_ovf[i];
            if (p.x == n) {
                float4 a = *(const float4*)&g_pk2[(size_t)p.y * 64];
                float e0 = lrelu_exp(a.x + aldv[0]);
                float e1 = lrelu_exp(a.y + aldv[1]);
                float e2 = lrelu_exp(a.z + aldv[2]);
                ssum0 += e0; ssum1 += e1; ssum2 += e2;
                if (act) {
                    float2 g = *(const float2*)&g_pk2[(size_t)p.y * 64 + 4 + c0];
                    float ww = (hd == 0) ? e0 : (hd == 1) ? e1 : e2;
                    acc.x += ww * g.x; acc.y += ww * g.y;
                }
            }
        }
    }
    // implicit self-loop (uniform)
    {
        float4 a = *(const float4*)&g_pk2[(size_t)n * 64];
        float e0 = lrelu_exp(a.x + aldv[0]);
        float e1 = lrelu_exp(a.y + aldv[1]);
        float e2 = lrelu_exp(a.z + aldv[2]);
        ssum0 += e0; ssum1 += e1; ssum2 += e2;
        if (act) {
            float2 g = *(const float2*)&g_pk2[(size_t)n * 64 + 4 + c0];
            float ww = (hd == 0) ? e0 : (hd == 1) ? e1 : e2;
            acc.x += ww * g.x; acc.y += ww * g.y;
        }
    }
    float2 o2 = make_float2(0.f, 0.f);
    if (act) {
        float ss = (hd == 0) ? ssum0 : (hd == 1) ? ssum1 : ssum2;
        float inv = 1.f / (ss + 1e-16f);
        o2.x = fmaxf(acc.x * inv + __ldg(&bias[c0]), 0.f);
        o2.y = fmaxf(acc.y * inv + __ldg(&bias[c0 + 1]), 0.f);
    }
    float t0 = 0.f, t1 = 0.f, t2 = 0.f, t3 = 0.f;
    if (act) {
        float4 wr0 = __ldg((const float4*)&W3[c0 * 4]);
        float4 wr1 = __ldg((const float4*)&W3[(c0 + 1) * 4]);
        t0 = o2.x * wr0.x + o2.y * wr1.x;
        t1 = o2.x * wr0.y + o2.y * wr1.y;
        t2 = o2.x * wr0.z + o2.y * wr1.z;
        t3 = o2.x * wr0.w + o2.y * wr1.w;
    }
    #pragma unroll
    for (int o = 16; o; o >>= 1) {
        t0 += __shfl_xor_sync(0xffffffffu, t0, o);
        t1 += __shfl_xor_sync(0xffffffffu, t1, o);
        t2 += __shfl_xor_sync(0xffffffffu, t2, o);
        t3 += __shfl_xor_sync(0xffffffffu, t3, o);
    }
    if (lane == 0) {
        *(float4*)&h3out[(size_t)n * 4] = make_float4(t0, t1, t2, t3);
        g_als3[n] = t0 * __ldg(&as3[0]) + t1 * __ldg(&as3[1]) + t2 * __ldg(&as3[2]) + t3 * __ldg(&as3[3]);
        g_ald3[n] = t0 * __ldg(&ad3[0]) + t1 * __ldg(&ad3[1]) + t2 * __ldg(&ad3[2]) + t3 * __ldg(&ad3[3]);
    }
}

// ---------------- 6: layer-3 agg + global max pool ----------------
__global__ void k_agg3(const float* __restrict__ hfeat,
                       const float* __restrict__ bias,
                       const void* __restrict__ batch) {
    int wid = (blockIdx.x * blockDim.x + threadIdx.x) >> 5;
    if (wid >= NN) return;
    int lane = threadIdx.x & 31;
    int sub = lane >> 2, c = lane & 3;
    int n = wid;
    int deg = g_cnt[n];
    int inslot = min(deg, SLOT);
    const int* slot = g_slot + (size_t)n * SLOT;
    float aldn = g_ald3[n];
    float acc = 0.f, wsum = 0.f;
    for (int e0 = 0; e0 < inslot; e0 += 8) {
        int e = e0 + sub;
        if (e < inslot) {
            int s = slot[e];
            float w = lrelu_exp(g_als3[s] + aldn);
            acc += w * __ldg(&hfeat[(size_t)s * 4 + c]);
            wsum += w;
        }
    }
    #pragma unroll
    for (int o = 4; o < 32; o <<= 1) {
        acc += __shfl_xor_sync(0xffffffffu, acc, o);
        wsum += __shfl_xor_sync(0xffffffffu, wsum, o);
    }
    // overflow edges (normally none)
    if (deg > SLOT) {
        int on = min(g_ovf_cnt, OVF_MAX);
        for (int i = 0; i < on; i++) {
            int2 p = g_ovf[i];
            if (p.x == n) {
                float w = lrelu_exp(g_als3[p.y] + aldn);
                acc += w * __ldg(&hfeat[(size_t)p.y * 4 + c]);
                wsum += w;
            }
        }
    }
    // implicit self-loop
    {
        float w = lrelu_exp(g_als3[n] + aldn);
        acc += w * __ldg(&hfeat[(size_t)n * 4 + c]);
        wsum += w;
    }
    if (lane < 4) {
        float o = acc / (wsum + 1e-16f) + __ldg(&bias[lane]);
        bool is64 = (g_nz == 0);
        int g = (int)ld_idx(batch, n, is64);
        atomicMax(&g_pool[g * 4 + lane], enc(o));
    }
}

// ---------------- 7: log-softmax + restore clean state ----------------
__global__ void k_final(float* __restrict__ out) {
    int b = blockIdx.x, t = threadIdx.x;
    if (b == 0) {
        float v[4];
        #pragma unroll
        for (int c = 0; c < 4; c++) {
            unsigned u = g_pool[t * 4 + c];
            v[c] = (u <= 0x007FFFFFu) ? -1e9f : dec(u);
        }
        float m = fmaxf(fmaxf(v[0], v[1]), fmaxf(v[2], v[3]));
        float s = 0.f;
        #pragma unroll
        for (int c = 0; c < 4; c++) s += expf(v[c] - m);
        float lse = m + logf(s);
        #pragma unroll
        for (int c = 0; c < 4; c++) out[t * 4 + c] = v[c] - lse;
        __syncthreads();
        #pragma unroll
        for (int c = 0; c < 4; c++) g_pool[t * 4 + c] = 0u;
    }
    if (b == 1 && t == 0) g_ovf_cnt = 0;
    int i = b * 256 + t;
    if (i < NN) g_cnt[i] = 0;
}

// ---------------- launch ----------------
extern "C" void kernel_launch(void* const* d_in, const int* in_sizes, int n_in,
                              void* d_out, int out_size) {
    const float* x   = (const float*)d_in[0];
    const void*  ei  = d_in[1];
    const void*  bat = d_in[2];
    const float* W1  = (const float*)d_in[3];
    const float* as1 = (const float*)d_in[4];
    const float* ad1 = (const float*)d_in[5];
    const float* b1  = (const float*)d_in[6];
    const float* W2  = (const float*)d_in[7];
    const float* as2 = (const float*)d_in[8];
    const float* ad2 = (const float*)d_in[9];
    const float* b2  = (const float*)d_in[10];
    const float* W3  = (const float*)d_in[11];
    const float* as3 = (const float*)d_in[12];
    const float* ad3 = (const float*)d_in[13];
    const float* b3  = (const float*)d_in[14];
    float* out = (float*)d_out;

    float* obuf;
    cudaGetSymbolAddress((void**)&obuf, g_o);

    k_alpha_x<<<(NN + 255) / 256, 256>>>(x, W1, as1, ad1, W2, (const int*)ei);  // 1
    k_fill<<<(NE + 255) / 256, 256>>>(ei);                                      // 2
    k_aggx<<<NN / 8, 256>>>();                                                  // 3
    k_gemm2f<<<NN / 64, 288>>>(b1, as2, ad2);                                   // 4 (profiled)
    k_agg2<<<NN / 8, 256>>>(b2, W3, as3, ad3, obuf);                            // 5
    k_agg3<<<NN / 8, 256>>>(obuf, b3, bat);                                     // 6
    k_final<<<(NN + 255) / 256, 256>>>(out);                                    // 7
}